// round 3
// baseline (speedup 1.0000x reference)
#include <cuda_runtime.h>
#include <math.h>

#define BB   32
#define SEQ  64
#define EMB  512
#define HID  512
#define NREG 196
#define VOC  32000
#define SQRTE 22.62741699796952f

// ---------------- device scratch (static; no runtime alloc) ----------------
__device__ float g_emb[BB * SEQ * EMB];     // 4 MB   [b][t][e]
__device__ float g_fmean[BB * EMB];
__device__ float g_h[BB * HID];
__device__ float g_c[BB * HID];
__device__ float g_xin[BB * 1024];          // [context | emb_t]
__device__ float g_x[BB * EMB];
__device__ float g_gates[BB * 4 * HID];
__device__ float g_H[BB * SEQ * HID];       // 4 MB   row m = b*64+t

// ---------------- helpers ----------------
__device__ __forceinline__ float warpsum(float v) {
    #pragma unroll
    for (int o = 16; o > 0; o >>= 1) v += __shfl_xor_sync(0xffffffffu, v, o);
    return v;
}
__device__ __forceinline__ float warpmax(float v) {
    #pragma unroll
    for (int o = 16; o > 0; o >>= 1) v = fmaxf(v, __shfl_xor_sync(0xffffffffu, v, o));
    return v;
}
// packed dual-FMA (FFMA2) — only reachable via PTX fma.rn.f32x2 on sm_10x
__device__ __forceinline__ void ffma2(float2& d, const float2& a, const float2& b) {
    asm("fma.rn.f32x2 %0, %1, %2, %0;"
        : "+l"(*reinterpret_cast<unsigned long long*>(&d))
        : "l"(*reinterpret_cast<const unsigned long long*>(&a)),
          "l"(*reinterpret_cast<const unsigned long long*>(&b)));
}

// ---------------- one-time prep ----------------
__global__ void k_embed(const int* __restrict__ caps, const float* __restrict__ embW) {
    int idx = blockIdx.x * 512 + threadIdx.x;          // 2048 blocks x 512
    int bt = idx >> 9, e = idx & 511;
    int c = caps[bt];
    g_emb[idx] = embW[c * 512 + e] * SQRTE;
}

__global__ void k_fmean(const float* __restrict__ F) {
    int b = blockIdx.x;                                 // 32 blocks x 256
    for (int e = threadIdx.x; e < EMB; e += 256) {
        const float* p = F + (size_t)b * NREG * EMB + e;
        float s = 0.f;
        #pragma unroll 4
        for (int n = 0; n < NREG; n++) s += p[(size_t)n * EMB];
        g_fmean[b * EMB + e] = s * (1.0f / NREG);
    }
}

__global__ void k_init(const float* __restrict__ hW, const float* __restrict__ hb,
                       const float* __restrict__ cW, const float* __restrict__ cb) {
    int w = (blockIdx.x << 3) + (threadIdx.x >> 5);     // 4096 blocks x 256 -> 32768 warps
    int lane = threadIdx.x & 31;
    int which = w >> 14;                                // 0 = h, 1 = c
    int bj = w & 16383;
    int b = bj >> 9, j = bj & 511;
    const float4* Wp = (const float4*)((which ? cW : hW) + (size_t)j * EMB);
    const float4* fp = (const float4*)(g_fmean + b * EMB);
    float s = 0.f;
    #pragma unroll
    for (int i = 0; i < 4; i++) {
        int id = lane + i * 32;
        float4 a = Wp[id], x = fp[id];
        s += a.x * x.x + a.y * x.y + a.z * x.z + a.w * x.w;
    }
    s = warpsum(s);
    if (lane == 0) {
        if (which) g_c[b * HID + j] = s + cb[j];
        else       g_h[b * HID + j] = s + hb[j];
    }
}

// ---------------- per-step: attention + context + xin ----------------
__global__ void k_attn(const float* __restrict__ F, int t) {
    int b = blockIdx.x, tid = threadIdx.x;
    int lane = tid & 31, w = tid >> 5;
    __shared__ float hs[512];
    __shared__ float sc[224];
    __shared__ float red[16];

    for (int i = tid; i < 512; i += 256) hs[i] = g_h[b * HID + i];
    __syncthreads();

    const float4* h4 = (const float4*)hs;
    for (int n = w; n < NREG; n += 8) {
        const float4* fr = (const float4*)(F + (size_t)(b * NREG + n) * EMB);
        float s = 0.f;
        #pragma unroll
        for (int i = 0; i < 4; i++) {
            int id = lane + i * 32;
            float4 a = fr[id], hh = h4[id];
            s += a.x * hh.x + a.y * hh.y + a.z * hh.z + a.w * hh.w;
        }
        s = warpsum(s);
        if (lane == 0) sc[n] = s;
    }
    __syncthreads();

    float v = (tid < NREG) ? sc[tid] : -3.4e38f;
    float m = warpmax(v);
    if (lane == 0) red[w] = m;
    __syncthreads();
    if (tid == 0) {
        float mm = red[0];
        for (int i = 1; i < 8; i++) mm = fmaxf(mm, red[i]);
        red[8] = mm;
    }
    __syncthreads();
    float mx = red[8];
    float ex = (tid < NREG) ? expf(v - mx) : 0.f;
    float s = warpsum(ex);
    if (lane == 0) red[w] = s;
    __syncthreads();
    if (tid == 0) {
        float tt = 0.f;
        for (int i = 0; i < 8; i++) tt += red[i];
        red[9] = 1.f / tt;
    }
    __syncthreads();
    if (tid < NREG) sc[tid] = ex * red[9];
    __syncthreads();

    for (int e = tid; e < EMB; e += 256) {
        const float* fp = F + (size_t)b * NREG * EMB + e;
        float acc = 0.f;
        #pragma unroll 4
        for (int n = 0; n < NREG; n++) acc += sc[n] * fp[(size_t)n * EMB];
        g_xin[b * 1024 + e]       = acc;
        g_xin[b * 1024 + 512 + e] = g_emb[((b << 6) + t) * EMB + e];
    }
}

// ---------------- per-step: x = xin @ reshape_W^T + b ----------------
__global__ void k_x(const float* __restrict__ rW, const float* __restrict__ rb) {
    int tid = threadIdx.x, lane = tid & 31, w = tid >> 5;
    int r = blockIdx.x * 8 + w;                         // 64 blocks x 8 warps -> 512 rows
    float4 wr[8];
    const float4* Wp = (const float4*)(rW + (size_t)r * 1024);
    #pragma unroll
    for (int i = 0; i < 8; i++) wr[i] = Wp[lane + i * 32];
    float bias = rb[r];
    __shared__ float4 xs[256];
    for (int b = 0; b < BB; b++) {
        __syncthreads();
        xs[tid] = ((const float4*)(g_xin + b * 1024))[tid];
        __syncthreads();
        float s = 0.f;
        #pragma unroll
        for (int i = 0; i < 8; i++) {
            float4 xv = xs[lane + i * 32];
            s += wr[i].x * xv.x + wr[i].y * xv.y + wr[i].z * xv.z + wr[i].w * xv.w;
        }
        s = warpsum(s);
        if (lane == 0) g_x[b * EMB + r] = s + bias;
    }
}

// ---------------- per-step: gates = x@Wih^T + h@Whh^T + biases ----------------
__global__ void k_gates(const float* __restrict__ Wih, const float* __restrict__ Whh,
                        const float* __restrict__ bih, const float* __restrict__ bhh) {
    int tid = threadIdx.x, lane = tid & 31, w = tid >> 5;
    int r = blockIdx.x * 8 + w;                         // 256 blocks -> 2048 rows
    float4 wi[4], wh[4];
    const float4* pi = (const float4*)(Wih + (size_t)r * 512);
    const float4* ph = (const float4*)(Whh + (size_t)r * 512);
    #pragma unroll
    for (int i = 0; i < 4; i++) { wi[i] = pi[lane + i * 32]; wh[i] = ph[lane + i * 32]; }
    float bias = bih[r] + bhh[r];
    __shared__ float4 xh[256];                          // [x(512) | h(512)]
    for (int b = 0; b < BB; b++) {
        __syncthreads();
        if (tid < 128) xh[tid] = ((const float4*)(g_x + b * 512))[tid];
        else           xh[tid] = ((const float4*)(g_h + b * 512))[tid - 128];
        __syncthreads();
        float s = 0.f;
        #pragma unroll
        for (int i = 0; i < 4; i++) {
            float4 xv = xh[lane + i * 32];
            s += wi[i].x * xv.x + wi[i].y * xv.y + wi[i].z * xv.z + wi[i].w * xv.w;
            float4 hv = xh[128 + lane + i * 32];
            s += wh[i].x * hv.x + wh[i].y * hv.y + wh[i].z * hv.z + wh[i].w * hv.w;
        }
        s = warpsum(s);
        if (lane == 0) g_gates[b * 2048 + r] = s + bias;
    }
}

// ---------------- per-step: LSTM cell update ----------------
__global__ void k_update(int t) {
    int b = blockIdx.x, j = threadIdx.x;                // 32 blocks x 512
    float gi = g_gates[b * 2048 + j];
    float gf = g_gates[b * 2048 + 512 + j];
    float gg = g_gates[b * 2048 + 1024 + j];
    float go = g_gates[b * 2048 + 1536 + j];
    float c  = g_c[b * HID + j];
    float si = 1.f / (1.f + expf(-gi));
    float sf = 1.f / (1.f + expf(-gf));
    float so = 1.f / (1.f + expf(-go));
    float c2 = sf * c + si * tanhf(gg);
    float h2 = so * tanhf(c2);
    g_c[b * HID + j] = c2;
    g_h[b * HID + j] = h2;
    g_H[(size_t)((b << 6) + t) * HID + j] = h2;         // row m = b*64+t
}

// ---------------- batched output GEMM: out[m][v] = H[m] . out_W[v] + out_b[v] ----
// C = [2048 x 32000], K=512. Tiles 128x128, BK=16, 256 threads, 8x8 micro-tile
// with f32x2 packed FMA along v (A duplicated as (a,a) pairs at fill time).
__global__ void k_out(const float* __restrict__ Wt, const float* __restrict__ ob,
                      float* __restrict__ out) {
    __shared__ float2 As2[16 * 129];                    // (a,a) pairs, padded
    __shared__ float  Bs [16 * 130];                    // padded, conflict-free
    int tid = threadIdx.x;
    int tx = tid & 15, ty = tid >> 4;
    int vt = blockIdx.x * 128;
    int mt = blockIdx.y * 128;

    float2 acc[8][4];
    #pragma unroll
    for (int i = 0; i < 8; i++)
        #pragma unroll
        for (int q = 0; q < 4; q++) acc[i][q] = make_float2(0.f, 0.f);

    for (int kc = 0; kc < 32; kc++) {
        __syncthreads();
        #pragma unroll
        for (int i = 0; i < 2; i++) {
            int f4 = tid + i * 256;                     // 512 float4 per operand
            int m = f4 >> 2, kk = f4 & 3;
            float4 a = *(const float4*)(g_H + (size_t)(mt + m) * 512 + kc * 16 + kk * 4);
            int kb = kk * 4;
            As2[(kb + 0) * 129 + m] = make_float2(a.x, a.x);
            As2[(kb + 1) * 129 + m] = make_float2(a.y, a.y);
            As2[(kb + 2) * 129 + m] = make_float2(a.z, a.z);
            As2[(kb + 3) * 129 + m] = make_float2(a.w, a.w);
            float4 bv = *(const float4*)(Wt + (size_t)(vt + m) * 512 + kc * 16 + kk * 4);
            Bs[(kb + 0) * 130 + m] = bv.x;
            Bs[(kb + 1) * 130 + m] = bv.y;
            Bs[(kb + 2) * 130 + m] = bv.z;
            Bs[(kb + 3) * 130 + m] = bv.w;
        }
        __syncthreads();
        #pragma unroll
        for (int k = 0; k < 16; k++) {
            float2 b2[4];
            #pragma unroll
            for (int q = 0; q < 4; q++)
                b2[q] = *(const float2*)&Bs[k * 130 + 2 * tx + 32 * q];
            #pragma unroll
            for (int i = 0; i < 8; i++) {
                float2 a2 = As2[k * 129 + ty * 8 + i];
                #pragma unroll
                for (int q = 0; q < 4; q++) ffma2(acc[i][q], a2, b2[q]);
            }
        }
    }
    #pragma unroll
    for (int q = 0; q < 4; q++) {
        int v = vt + 2 * tx + 32 * q;
        float2 bb = *(const float2*)(ob + v);
        #pragma unroll
        for (int i = 0; i < 8; i++) {
            int m = mt + ty * 8 + i;
            float2 r = make_float2(acc[i][q].x + bb.x, acc[i][q].y + bb.y);
            *(float2*)(out + (size_t)m * VOC + v) = r;
        }
    }
}

// ---------------- launch ----------------
extern "C" void kernel_launch(void* const* d_in, const int* in_sizes, int n_in,
                              void* d_out, int out_size) {
    const float* features = (const float*)d_in[0];
    const int*   captions = (const int*)  d_in[1];
    const float* embW     = (const float*)d_in[2];
    const float* ihW      = (const float*)d_in[3];
    const float* ihb      = (const float*)d_in[4];
    const float* icW      = (const float*)d_in[5];
    const float* icb      = (const float*)d_in[6];
    const float* rW       = (const float*)d_in[7];
    const float* rb       = (const float*)d_in[8];
    const float* Wih      = (const float*)d_in[9];
    const float* Whh      = (const float*)d_in[10];
    const float* bih      = (const float*)d_in[11];
    const float* bhh      = (const float*)d_in[12];
    const float* oW       = (const float*)d_in[13];
    const float* ob       = (const float*)d_in[14];
    float* out = (float*)d_out;

    k_embed<<<2048, 512>>>(captions, embW);
    k_fmean<<<32, 256>>>(features);
    k_init <<<4096, 256>>>(ihW, ihb, icW, icb);
    for (int t = 0; t < SEQ; t++) {
        k_attn  <<<32, 256>>>(features, t);
        k_x     <<<64, 256>>>(rW, rb);
        k_gates <<<256, 256>>>(Wih, Whh, bih, bhh);
        k_update<<<32, 512>>>(t);
    }
    k_out<<<dim3(250, 16), 256>>>(oW, ob, out);
}

// round 6
// speedup vs baseline: 1.0947x; 1.0947x over previous
#include <cuda_runtime.h>
#include <math.h>

#define BB   32
#define SEQ  64
#define EMB  512
#define HID  512
#define NREG 196
#define VOC  32000
#define SQRTE 22.62741699796952f
#define NCTA 148

// ---------------- device scratch (static; no runtime alloc) ----------------
__device__ float g_emb[BB * SEQ * EMB];     // 4 MB   [b][t][e], row m=b*64+t
__device__ float g_fmean[BB * EMB];
__device__ float g_h[BB * HID];
__device__ float g_c[BB * HID];
__device__ float g_x[BB * EMB];
__device__ float g_sc[BB * NREG];
__device__ float g_ctx[BB * EMB];
__device__ float g_gh[BB * 4 * HID];
__device__ float g_xe[BB * SEQ * EMB];      // 4 MB  precomputed emb-half of reshape (+bias)
__device__ float g_H[BB * SEQ * HID];       // 4 MB  row m = b*64+t
__device__ unsigned g_arrive;

// ---------------- helpers ----------------
__device__ __forceinline__ float allsum(float v) {
    #pragma unroll
    for (int o = 16; o > 0; o >>= 1) v += __shfl_xor_sync(0xffffffffu, v, o);
    return v;
}
__device__ __forceinline__ float allmax(float v) {
    #pragma unroll
    for (int o = 16; o > 0; o >>= 1) v = fmaxf(v, __shfl_xor_sync(0xffffffffu, v, o));
    return v;
}
// packed dual-FMA (FFMA2) — only reachable via PTX fma.rn.f32x2 on sm_10x
__device__ __forceinline__ void ffma2(float2& d, const float2& a, const float2& b) {
    asm("fma.rn.f32x2 %0, %1, %2, %0;"
        : "+l"(*reinterpret_cast<unsigned long long*>(&d))
        : "l"(*reinterpret_cast<const unsigned long long*>(&a)),
          "l"(*reinterpret_cast<const unsigned long long*>(&b)));
}
__device__ __forceinline__ void dotacc(float2& acc, const float4& w, const float4& v) {
    float2 a0 = make_float2(w.x, w.y), b0 = make_float2(v.x, v.y);
    ffma2(acc, a0, b0);
    float2 a1 = make_float2(w.z, w.w), b1 = make_float2(v.z, v.w);
    ffma2(acc, a1, b1);
}

// grid-wide software barrier: requires grid == NCTA <= #SMs (all co-resident)
__device__ __forceinline__ void gbar(unsigned& ep) {
    ep += NCTA;
    __threadfence();                 // push this thread's writes (gpu scope)
    __syncthreads();
    if (threadIdx.x == 0) {
        atomicAdd(&g_arrive, 1u);
        volatile unsigned* p = &g_arrive;
        while (*p < ep) { }
        __threadfence();             // acquire + L1 invalidate (CCTL.IVALL)
    }
    __syncthreads();
}

// ---------------- one-time prep ----------------
__global__ void k_embed(const int* __restrict__ caps, const float* __restrict__ embW) {
    if (blockIdx.x == 0 && threadIdx.x == 0) g_arrive = 0;   // barrier reset each launch
    int idx = blockIdx.x * 512 + threadIdx.x;                // 2048 blocks x 512
    int bt = idx >> 9, e = idx & 511;
    int c = caps[bt];
    g_emb[idx] = embW[c * 512 + e] * SQRTE;
}

__global__ void k_fmean(const float* __restrict__ F) {
    int b = blockIdx.x;                                      // 32 blocks x 256
    for (int e = threadIdx.x; e < EMB; e += 256) {
        const float* p = F + (size_t)b * NREG * EMB + e;
        float s = 0.f;
        #pragma unroll 4
        for (int n = 0; n < NREG; n++) s += p[(size_t)n * EMB];
        g_fmean[b * EMB + e] = s * (1.0f / NREG);
    }
}

__global__ void k_init(const float* __restrict__ hW, const float* __restrict__ hb,
                       const float* __restrict__ cW, const float* __restrict__ cb) {
    int w = (blockIdx.x << 3) + (threadIdx.x >> 5);          // 4096 blocks x 256
    int lane = threadIdx.x & 31;
    int which = w >> 14;                                     // 0 = h, 1 = c
    int bj = w & 16383;
    int b = bj >> 9, j = bj & 511;
    const float4* Wp = (const float4*)((which ? cW : hW) + (size_t)j * EMB);
    const float4* fp = (const float4*)(g_fmean + b * EMB);
    float s = 0.f;
    #pragma unroll
    for (int i = 0; i < 4; i++) {
        int id = lane + i * 32;
        float4 a = Wp[id], x = fp[id];
        s += a.x * x.x + a.y * x.y + a.z * x.z + a.w * x.w;
    }
    s = allsum(s);
    if (lane == 0) {
        if (which) g_c[b * HID + j] = s + cb[j];
        else       g_h[b * HID + j] = s + hb[j];
    }
}

// ---------------- precompute emb-half of reshape: xe = emb @ rW[:,512:]^T + rb ----
// C = [2048 x 512], K = 512. Same tiling as k_out.
__global__ void k_xe(const float* __restrict__ rW, const float* __restrict__ rb) {
    __shared__ float2 As2[16 * 129];
    __shared__ float  Bs [16 * 130];
    int tid = threadIdx.x;
    int tx = tid & 15, ty = tid >> 4;
    int vt = blockIdx.x * 128;                              // 4 blocks
    int mt = blockIdx.y * 128;                              // 16 blocks

    float2 acc[8][4];
    #pragma unroll
    for (int i = 0; i < 8; i++)
        #pragma unroll
        for (int q = 0; q < 4; q++) acc[i][q] = make_float2(0.f, 0.f);

    for (int kc = 0; kc < 32; kc++) {
        __syncthreads();
        #pragma unroll
        for (int i = 0; i < 2; i++) {
            int f4 = tid + i * 256;
            int m = f4 >> 2, kk = f4 & 3;
            float4 a = *(const float4*)(g_emb + (size_t)(mt + m) * 512 + kc * 16 + kk * 4);
            int kb = kk * 4;
            As2[(kb + 0) * 129 + m] = make_float2(a.x, a.x);
            As2[(kb + 1) * 129 + m] = make_float2(a.y, a.y);
            As2[(kb + 2) * 129 + m] = make_float2(a.z, a.z);
            As2[(kb + 3) * 129 + m] = make_float2(a.w, a.w);
            float4 bv = *(const float4*)(rW + (size_t)(vt + m) * 1024 + 512 + kc * 16 + kk * 4);
            Bs[(kb + 0) * 130 + m] = bv.x;
            Bs[(kb + 1) * 130 + m] = bv.y;
            Bs[(kb + 2) * 130 + m] = bv.z;
            Bs[(kb + 3) * 130 + m] = bv.w;
        }
        __syncthreads();
        #pragma unroll
        for (int k = 0; k < 16; k++) {
            float2 b2[4];
            #pragma unroll
            for (int q = 0; q < 4; q++)
                b2[q] = *(const float2*)&Bs[k * 130 + 2 * tx + 32 * q];
            #pragma unroll
            for (int i = 0; i < 8; i++) {
                float2 a2 = As2[k * 129 + ty * 8 + i];
                #pragma unroll
                for (int q = 0; q < 4; q++) ffma2(acc[i][q], a2, b2[q]);
            }
        }
    }
    #pragma unroll
    for (int q = 0; q < 4; q++) {
        int v = vt + 2 * tx + 32 * q;
        float2 bb = *(const float2*)(rb + v);
        #pragma unroll
        for (int i = 0; i < 8; i++) {
            int m = mt + ty * 8 + i;
            float2 r = make_float2(acc[i][q].x + bb.x, acc[i][q].y + bb.y);
            *(float2*)(g_xe + (size_t)m * 512 + v) = r;
        }
    }
}

// ---------------- persistent fused recurrence ----------------
// grid = 148 CTAs x 256 thr.  dyn smem: R1[16384] + abuf[1792] floats = 72704 B
__global__ void __launch_bounds__(256, 1)
k_rec(const float* __restrict__ F, const float* __restrict__ rW,
      const float* __restrict__ Wih, const float* __restrict__ Whh,
      const float* __restrict__ bih, const float* __restrict__ bhh) {
    extern __shared__ float sm[];
    float* R1   = sm;                // 16384 floats: h / ctx / x staging (all 32 b)
    float* abuf = sm + 16384;        // per-warp attention weights (w<4): 4*224 used
    const int tid = threadIdx.x, lane = tid & 31, w = tid >> 5;
    const int cta = blockIdx.x;
    unsigned ep = 0;

    // phase-C persistent state: warp owns hidden unit q (gate rows q,q+512,q+1024,q+1536)
    const int q = cta + NCTA * w;
    const bool hasq = (w < 4) && (q < 512);
    float c_l = 0.f;                 // lane b holds c[b][q] in a register, forever
    float biasq[4] = {0.f, 0.f, 0.f, 0.f};
    if (hasq) {
        c_l = __ldcg(&g_c[lane * 512 + q]);
        #pragma unroll
        for (int g = 0; g < 4; g++) biasq[g] = bih[q + g * 512] + bhh[q + g * 512];
    }

    for (int t = 0; t < SEQ; t++) {
        // ======== Phase A: stage h; gh = h@Whh^T (w<7); scores (w==7) ========
        {
            const float4* hg = (const float4*)g_h;
            float4* R14 = (float4*)R1;
            for (int i = tid; i < 4096; i += 256) R14[i] = __ldcg(hg + i);
            __syncthreads();
            if (w < 7) {
                int p = cta + NCTA * w;
                if (p < 1024) {
                    int r0 = 2 * p;
                    const float4* p0 = (const float4*)(Whh + (size_t)r0 * 512);
                    float4 w0[4], w1[4];
                    #pragma unroll
                    for (int i = 0; i < 4; i++) {
                        w0[i] = p0[lane + i * 32];
                        w1[i] = p0[128 + lane + i * 32];
                    }
                    for (int b = 0; b < 32; b++) {
                        const float4* hb = (const float4*)(R1 + b * 512);
                        float2 a0 = make_float2(0.f, 0.f), a1 = make_float2(0.f, 0.f);
                        #pragma unroll
                        for (int i = 0; i < 4; i++) {
                            float4 hv = hb[lane + i * 32];
                            dotacc(a0, w0[i], hv);
                            dotacc(a1, w1[i], hv);
                        }
                        float s0 = allsum(a0.x + a0.y), s1 = allsum(a1.x + a1.y);
                        if (lane == 0) {
                            g_gh[b * 2048 + r0]     = s0;
                            g_gh[b * 2048 + r0 + 1] = s1;
                        }
                    }
                }
            } else {
                for (int d = cta; d < BB * NREG; d += NCTA) {
                    int b = d / NREG, n = d - b * NREG;
                    const float4* fr = (const float4*)(F + (size_t)(b * NREG + n) * 512);
                    const float4* hb = (const float4*)(R1 + b * 512);
                    float2 a = make_float2(0.f, 0.f);
                    #pragma unroll
                    for (int i = 0; i < 4; i++) dotacc(a, fr[lane + i * 32], hb[lane + i * 32]);
                    float s = allsum(a.x + a.y);
                    if (lane == 0) g_sc[d] = s;
                }
            }
        }
        gbar(ep);
        // ======== Phase B1: softmax (redundant per warp) + context ========
        if (w < 4) {
            int task = cta + NCTA * w;
            if (task < 512) {
                int b = task >> 4, ec = task & 15;
                float ev[7];
                float mx = -3.4e38f;
                #pragma unroll
                for (int j = 0; j < 7; j++) {
                    int n = lane + j * 32;
                    float s = (n < NREG) ? __ldcg(&g_sc[b * NREG + n]) : -3.4e38f;
                    ev[j] = s;
                    mx = fmaxf(mx, s);
                }
                mx = allmax(mx);
                float sum = 0.f;
                #pragma unroll
                for (int j = 0; j < 7; j++) {
                    int n = lane + j * 32;
                    float e = (n < NREG) ? expf(ev[j] - mx) : 0.f;
                    ev[j] = e;
                    sum += e;
                }
                sum = allsum(sum);
                float inv = 1.f / sum;
                float* ab = abuf + w * 224;
                #pragma unroll
                for (int j = 0; j < 7; j++) {
                    int n = lane + j * 32;
                    if (n < NREG) ab[n] = ev[j] * inv;
                }
                __syncwarp();
                const float* fp = F + (size_t)b * NREG * EMB + ec * 32 + lane;
                float acc = 0.f;
                #pragma unroll 4
                for (int n = 0; n < NREG; n++) acc = fmaf(ab[n], fp[(size_t)n * EMB], acc);
                g_ctx[b * 512 + ec * 32 + lane] = acc;
            }
        }
        gbar(ep);
        // ======== Phase B2: x = ctx @ rW[:, :512]^T + xe[b][t] ========
        {
            float4* R14 = (float4*)R1;
            const float4* cg = (const float4*)g_ctx;
            for (int i = tid; i < 4096; i += 256) R14[i] = __ldcg(cg + i);
            __syncthreads();
            int r = cta + NCTA * w;
            if (w < 4 && r < 512) {
                const float4* p = (const float4*)(rW + (size_t)r * 1024);
                float4 wr[4];
                #pragma unroll
                for (int i = 0; i < 4; i++) wr[i] = p[lane + i * 32];
                for (int b = 0; b < 32; b++) {
                    const float4* xb = (const float4*)(R1 + b * 512);
                    float2 a = make_float2(0.f, 0.f);
                    #pragma unroll
                    for (int i = 0; i < 4; i++) dotacc(a, wr[i], xb[lane + i * 32]);
                    float s = allsum(a.x + a.y);
                    if (lane == 0)
                        g_x[b * 512 + r] = s + g_xe[(size_t)(b * 64 + t) * 512 + r];
                }
            }
        }
        gbar(ep);
        // ======== Phase C: gates (x-half) + gh + LSTM update, fused ========
        {
            float4* R14 = (float4*)R1;
            const float4* xg = (const float4*)g_x;
            for (int i = tid; i < 4096; i += 256) R14[i] = __ldcg(xg + i);
            __syncthreads();
            if (hasq) {
                const float4* p0 = (const float4*)(Wih + (size_t)q * 512);
                float4 wi0[4], wi1[4], wi2[4], wi3[4];
                #pragma unroll
                for (int i = 0; i < 4; i++) {
                    wi0[i] = p0[lane + i * 32];
                    wi1[i] = p0[65536  + lane + i * 32];
                    wi2[i] = p0[131072 + lane + i * 32];
                    wi3[i] = p0[196608 + lane + i * 32];
                }
                float ghr[4];
                #pragma unroll
                for (int g = 0; g < 4; g++)
                    ghr[g] = __ldcg(&g_gh[lane * 2048 + q + g * 512]);
                for (int b = 0; b < 32; b++) {
                    const float4* xb = (const float4*)(R1 + b * 512);
                    float2 a0 = make_float2(0.f, 0.f), a1 = make_float2(0.f, 0.f);
                    float2 a2 = make_float2(0.f, 0.f), a3 = make_float2(0.f, 0.f);
                    #pragma unroll
                    for (int i = 0; i < 4; i++) {
                        float4 xv = xb[lane + i * 32];
                        dotacc(a0, wi0[i], xv);
                        dotacc(a1, wi1[i], xv);
                        dotacc(a2, wi2[i], xv);
                        dotacc(a3, wi3[i], xv);
                    }
                    float s0 = allsum(a0.x + a0.y), s1 = allsum(a1.x + a1.y);
                    float s2 = allsum(a2.x + a2.y), s3 = allsum(a3.x + a3.y);
                    if (lane == b) {
                        float gi = s0 + ghr[0] + biasq[0];
                        float gf = s1 + ghr[1] + biasq[1];
                        float gg = s2 + ghr[2] + biasq[2];
                        float go = s3 + ghr[3] + biasq[3];
                        float si = 1.f / (1.f + expf(-gi));
                        float sf = 1.f / (1.f + expf(-gf));
                        float so = 1.f / (1.f + expf(-go));
                        c_l = sf * c_l + si * tanhf(gg);
                        float h2 = so * tanhf(c_l);
                        g_h[b * 512 + q] = h2;
                        g_H[(size_t)(b * 64 + t) * 512 + q] = h2;
                    }
                }
            }
        }
        gbar(ep);
    }
}

// ---------------- batched output GEMM: out[m][v] = H[m] . out_W[v] + out_b[v] ----
__global__ void k_out(const float* __restrict__ Wt, const float* __restrict__ ob,
                      float* __restrict__ out) {
    __shared__ float2 As2[16 * 129];
    __shared__ float  Bs [16 * 130];
    int tid = threadIdx.x;
    int tx = tid & 15, ty = tid >> 4;
    int vt = blockIdx.x * 128;
    int mt = blockIdx.y * 128;

    float2 acc[8][4];
    #pragma unroll
    for (int i = 0; i < 8; i++)
        #pragma unroll
        for (int q = 0; q < 4; q++) acc[i][q] = make_float2(0.f, 0.f);

    for (int kc = 0; kc < 32; kc++) {
        __syncthreads();
        #pragma unroll
        for (int i = 0; i < 2; i++) {
            int f4 = tid + i * 256;
            int m = f4 >> 2, kk = f4 & 3;
            float4 a = *(const float4*)(g_H + (size_t)(mt + m) * 512 + kc * 16 + kk * 4);
            int kb = kk * 4;
            As2[(kb + 0) * 129 + m] = make_float2(a.x, a.x);
            As2[(kb + 1) * 129 + m] = make_float2(a.y, a.y);
            As2[(kb + 2) * 129 + m] = make_float2(a.z, a.z);
            As2[(kb + 3) * 129 + m] = make_float2(a.w, a.w);
            float4 bv = *(const float4*)(Wt + (size_t)(vt + m) * 512 + kc * 16 + kk * 4);
            Bs[(kb + 0) * 130 + m] = bv.x;
            Bs[(kb + 1) * 130 + m] = bv.y;
            Bs[(kb + 2) * 130 + m] = bv.z;
            Bs[(kb + 3) * 130 + m] = bv.w;
        }
        __syncthreads();
        #pragma unroll
        for (int k = 0; k < 16; k++) {
            float2 b2[4];
            #pragma unroll
            for (int q = 0; q < 4; q++)
                b2[q] = *(const float2*)&Bs[k * 130 + 2 * tx + 32 * q];
            #pragma unroll
            for (int i = 0; i < 8; i++) {
                float2 a2 = As2[k * 129 + ty * 8 + i];
                #pragma unroll
                for (int q = 0; q < 4; q++) ffma2(acc[i][q], a2, b2[q]);
            }
        }
    }
    #pragma unroll
    for (int q = 0; q < 4; q++) {
        int v = vt + 2 * tx + 32 * q;
        float2 bb = *(const float2*)(ob + v);
        #pragma unroll
        for (int i = 0; i < 8; i++) {
            int m = mt + ty * 8 + i;
            float2 r = make_float2(acc[i][q].x + bb.x, acc[i][q].y + bb.y);
            *(float2*)(out + (size_t)m * VOC + v) = r;
        }
    }
}

// ---------------- launch ----------------
extern "C" void kernel_launch(void* const* d_in, const int* in_sizes, int n_in,
                              void* d_out, int out_size) {
    const float* features = (const float*)d_in[0];
    const int*   captions = (const int*)  d_in[1];
    const float* embW     = (const float*)d_in[2];
    const float* ihW      = (const float*)d_in[3];
    const float* ihb      = (const float*)d_in[4];
    const float* icW      = (const float*)d_in[5];
    const float* icb      = (const float*)d_in[6];
    const float* rW       = (const float*)d_in[7];
    const float* rb       = (const float*)d_in[8];
    const float* Wih      = (const float*)d_in[9];
    const float* Whh      = (const float*)d_in[10];
    const float* bih      = (const float*)d_in[11];
    const float* bhh      = (const float*)d_in[12];
    const float* oW       = (const float*)d_in[13];
    const float* ob       = (const float*)d_in[14];
    float* out = (float*)d_out;

    static int smem_set = 0;
    if (!smem_set) {
        cudaFuncSetAttribute(k_rec, cudaFuncAttributeMaxDynamicSharedMemorySize, 73728);
        smem_set = 1;
    }

    k_embed<<<2048, 512>>>(captions, embW);       // also resets grid barrier counter
    k_xe   <<<dim3(4, 16), 256>>>(rW, rb);        // emb-half of reshape, hoisted
    k_fmean<<<32, 256>>>(features);
    k_init <<<4096, 256>>>(ihW, ihb, icW, icb);
    k_rec  <<<NCTA, 256, 72704>>>(features, rW, Wih, Whh, bih, bhh);
    k_out  <<<dim3(250, 16), 256>>>(oW, ob, out);
}

// round 7
// speedup vs baseline: 1.2101x; 1.1054x over previous
#include <cuda_runtime.h>
#include <math.h>

#define BB   32
#define SEQ  64
#define EMB  512
#define HID  512
#define NREG 196
#define VOC  32000
#define SQRTE 22.62741699796952f
#define NCTA 148

// ---------------- device scratch (static; no runtime alloc) ----------------
__device__ float g_emb[BB * SEQ * EMB];       // 4 MB  [m][e], m = b*64+t
__device__ float g_fmean[BB * EMB];
__device__ float g_h[BB * HID];
__device__ float g_c[BB * HID];
__device__ float g_sc[BB * NREG];
__device__ float g_ctx[BB * EMB];
__device__ float g_xe[BB * SEQ * EMB];        // 4 MB  emb-half of reshape (+rb)
__device__ float g_H[BB * SEQ * HID];         // 4 MB  row m = b*64+t
__device__ float g_rWT[EMB * EMB];            // 1 MB  rW[:, :512] transposed
__device__ float g_M[4 * HID * EMB];          // 4 MB  M = Wih @ rW1
__device__ float g_pre2T[SEQ * 4 * HID * BB]; // 16 MB pre2T[t][r][b]
__device__ unsigned g_arrive;

// ---------------- helpers ----------------
__device__ __forceinline__ float allsum(float v) {
    #pragma unroll
    for (int o = 16; o > 0; o >>= 1) v += __shfl_xor_sync(0xffffffffu, v, o);
    return v;
}
__device__ __forceinline__ float allmax(float v) {
    #pragma unroll
    for (int o = 16; o > 0; o >>= 1) v = fmaxf(v, __shfl_xor_sync(0xffffffffu, v, o));
    return v;
}
// packed dual-FMA (FFMA2) — only reachable via PTX fma.rn.f32x2 on sm_10x
__device__ __forceinline__ void ffma2(float2& d, const float2& a, const float2& b) {
    asm("fma.rn.f32x2 %0, %1, %2, %0;"
        : "+l"(*reinterpret_cast<unsigned long long*>(&d))
        : "l"(*reinterpret_cast<const unsigned long long*>(&a)),
          "l"(*reinterpret_cast<const unsigned long long*>(&b)));
}
__device__ __forceinline__ void dotacc(float2& acc, const float4& w, const float4& v) {
    float2 a0 = make_float2(w.x, w.y), b0 = make_float2(v.x, v.y);
    ffma2(acc, a0, b0);
    float2 a1 = make_float2(w.z, w.w), b1 = make_float2(v.z, v.w);
    ffma2(acc, a1, b1);
}

// grid-wide software barrier: requires grid == NCTA <= #SMs (all co-resident)
__device__ __forceinline__ void gbar(unsigned& ep) {
    ep += NCTA;
    __threadfence();
    __syncthreads();
    if (threadIdx.x == 0) {
        atomicAdd(&g_arrive, 1u);
        volatile unsigned* p = &g_arrive;
        while (*p < ep) { }
        __threadfence();
    }
    __syncthreads();
}

// ---------------- one-time prep ----------------
__global__ void k_embed(const int* __restrict__ caps, const float* __restrict__ embW) {
    if (blockIdx.x == 0 && threadIdx.x == 0) g_arrive = 0;   // barrier reset each launch
    int idx = blockIdx.x * 512 + threadIdx.x;
    int bt = idx >> 9, e = idx & 511;
    int c = caps[bt];
    g_emb[idx] = embW[c * 512 + e] * SQRTE;
}

__global__ void k_trans(const float* __restrict__ rW) {   // g_rWT[k][j] = rW[j][k], k<512
    __shared__ float tile[32][33];
    int bk = blockIdx.x * 32, bj = blockIdx.y * 32;
    int tx = threadIdx.x, ty0 = threadIdx.y;               // 32 x 8
    #pragma unroll
    for (int i = 0; i < 4; i++) {
        int ty = ty0 + i * 8;
        tile[ty][tx] = rW[(size_t)(bj + ty) * 1024 + bk + tx];
    }
    __syncthreads();
    #pragma unroll
    for (int i = 0; i < 4; i++) {
        int ty = ty0 + i * 8;
        g_rWT[(size_t)(bk + ty) * 512 + bj + tx] = tile[tx][ty];
    }
}

__global__ void k_fmean(const float* __restrict__ F) {
    int b = blockIdx.x;
    for (int e = threadIdx.x; e < EMB; e += 256) {
        const float* p = F + (size_t)b * NREG * EMB + e;
        float s = 0.f;
        #pragma unroll 4
        for (int n = 0; n < NREG; n++) s += p[(size_t)n * EMB];
        g_fmean[b * EMB + e] = s * (1.0f / NREG);
    }
}

__global__ void k_init(const float* __restrict__ hW, const float* __restrict__ hb,
                       const float* __restrict__ cW, const float* __restrict__ cb) {
    int w = (blockIdx.x << 3) + (threadIdx.x >> 5);
    int lane = threadIdx.x & 31;
    int which = w >> 14;
    int bj = w & 16383;
    int b = bj >> 9, j = bj & 511;
    const float4* Wp = (const float4*)((which ? cW : hW) + (size_t)j * EMB);
    const float4* fp = (const float4*)(g_fmean + b * EMB);
    float s = 0.f;
    #pragma unroll
    for (int i = 0; i < 4; i++) {
        int id = lane + i * 32;
        float4 a = Wp[id], x = fp[id];
        s += a.x * x.x + a.y * x.y + a.z * x.z + a.w * x.w;
    }
    s = allsum(s);
    if (lane == 0) {
        if (which) g_c[b * HID + j] = s + cb[j];
        else       g_h[b * HID + j] = s + hb[j];
    }
}

// ---------------- generic 128x128 FFMA2 GEMM: C[m][v] = A[m] . Brow[v] (+bias) --
// K = 512 always. transout=1 writes pre2T layout [(m&63)*2048+v]*32 + (m>>6).
__global__ void k_gemm(const float* __restrict__ A, int lda,
                       const float* __restrict__ Bm, int ldb,
                       const float* __restrict__ bias,
                       float* __restrict__ C, int ldc, int transout) {
    __shared__ float2 As2[16 * 129];
    __shared__ float  Bs [16 * 130];
    int tid = threadIdx.x;
    int tx = tid & 15, ty = tid >> 4;
    int vt = blockIdx.x * 128;
    int mt = blockIdx.y * 128;

    float2 acc[8][4];
    #pragma unroll
    for (int i = 0; i < 8; i++)
        #pragma unroll
        for (int q = 0; q < 4; q++) acc[i][q] = make_float2(0.f, 0.f);

    for (int kc = 0; kc < 32; kc++) {
        __syncthreads();
        #pragma unroll
        for (int i = 0; i < 2; i++) {
            int f4 = tid + i * 256;
            int m = f4 >> 2, kk = f4 & 3;
            float4 a = *(const float4*)(A + (size_t)(mt + m) * lda + kc * 16 + kk * 4);
            int kb = kk * 4;
            As2[(kb + 0) * 129 + m] = make_float2(a.x, a.x);
            As2[(kb + 1) * 129 + m] = make_float2(a.y, a.y);
            As2[(kb + 2) * 129 + m] = make_float2(a.z, a.z);
            As2[(kb + 3) * 129 + m] = make_float2(a.w, a.w);
            float4 bv = *(const float4*)(Bm + (size_t)(vt + m) * ldb + kc * 16 + kk * 4);
            Bs[(kb + 0) * 130 + m] = bv.x;
            Bs[(kb + 1) * 130 + m] = bv.y;
            Bs[(kb + 2) * 130 + m] = bv.z;
            Bs[(kb + 3) * 130 + m] = bv.w;
        }
        __syncthreads();
        #pragma unroll
        for (int k = 0; k < 16; k++) {
            float2 b2[4];
            #pragma unroll
            for (int q = 0; q < 4; q++)
                b2[q] = *(const float2*)&Bs[k * 130 + 2 * tx + 32 * q];
            #pragma unroll
            for (int i = 0; i < 8; i++) {
                float2 a2 = As2[k * 129 + ty * 8 + i];
                #pragma unroll
                for (int q = 0; q < 4; q++) ffma2(acc[i][q], a2, b2[q]);
            }
        }
    }
    #pragma unroll
    for (int q = 0; q < 4; q++) {
        int v = vt + 2 * tx + 32 * q;
        float2 bb = bias ? *(const float2*)(bias + v) : make_float2(0.f, 0.f);
        #pragma unroll
        for (int i = 0; i < 8; i++) {
            int m = mt + ty * 8 + i;
            float2 r = make_float2(acc[i][q].x + bb.x, acc[i][q].y + bb.y);
            if (!transout) {
                *(float2*)(C + (size_t)m * ldc + v) = r;
            } else {
                size_t base = ((size_t)((m & 63) * 2048 + v)) * 32 + (m >> 6);
                C[base]      = r.x;
                C[base + 32] = r.y;
            }
        }
    }
}

// ---------------- persistent fused recurrence ----------------
// grid = 148 CTAs x 256 thr. dyn smem 204288 B:
//   act4[256*33] float4  (hT rows 0..127, ctxT rows 128..255; [k4][b], pad 33)
//   ws2 [8192]   float2  (paired gate weights, staged once)
//   abuf[4*224]  float   (per-warp attention weights)
__global__ void __launch_bounds__(256, 1)
k_rec(const float* __restrict__ F, const float* __restrict__ Whh,
      const float* __restrict__ bih, const float* __restrict__ bhh) {
    extern __shared__ float4 smem4[];
    float4* act4 = smem4;
    float2* ws2  = (float2*)(smem4 + 256 * 33);
    float*  abuf = (float*)(ws2 + 8192);
    const int tid = threadIdx.x, lane = tid & 31, w = tid >> 5;
    const int cta = blockIdx.x;
    unsigned ep = 0;

    // persistent per-warp LSTM unit: warp (w<4) owns hidden unit q
    const int q = cta + NCTA * w;
    const bool hasq = (w < 4) && (q < 512);
    float c_l = 0.f;
    float biasq[4] = {0.f, 0.f, 0.f, 0.f};
    if (hasq) {
        c_l = __ldcg(&g_c[lane * 512 + q]);
        #pragma unroll
        for (int g = 0; g < 4; g++) biasq[g] = bih[q + g * 512] + bhh[q + g * 512];
        // stage paired weights once: src0 = M (vs ctx), src1 = Whh (vs h)
        #pragma unroll
        for (int s = 0; s < 2; s++) {
            #pragma unroll
            for (int p = 0; p < 2; p++) {
                const float* rA = (s ? Whh : g_M) + (size_t)(q + (p ? 1024 : 0))  * 512;
                const float* rB = (s ? Whh : g_M) + (size_t)(q + (p ? 1536 : 512)) * 512;
                float2* dst = ws2 + (size_t)(((w * 2 + s) * 2) + p) * 512;
                for (int j = lane; j < 512; j += 32)
                    dst[j] = make_float2(rA[j], rB[j]);
            }
        }
    }
    const float4* F4 = (const float4*)F;
    const int gw = cta * 8 + w;                       // 0..1183

    for (int t = 0; t < SEQ; t++) {
        // ======== Phase A: stage hT; scores over all 8 warps ========
        {
            const float4* hg = (const float4*)g_h;
            for (int i = tid; i < 4096; i += 256) {
                float4 v = __ldcg(hg + i);
                act4[(i & 127) * 33 + (i >> 7)] = v;  // [k4][b]
            }
            __syncthreads();
            for (int d = gw; d < BB * NREG; d += 1184) {
                int b = d / NREG;
                const float4* fr = F4 + (size_t)d * 128;
                float2 a = make_float2(0.f, 0.f);
                #pragma unroll
                for (int i = 0; i < 4; i++)
                    dotacc(a, fr[lane + 32 * i], act4[(lane + 32 * i) * 33 + b]);
                float s = allsum(a.x + a.y);
                if (lane == 0) g_sc[d] = s;
            }
        }
        gbar(ep);
        // ======== Phase B: softmax (redundant per warp) + context ========
        {
            int task = cta + NCTA * w;
            if (w < 4 && task < 512) {
                int b = task >> 4, ec = task & 15;
                float ev[7];
                float mx = -3.4e38f;
                #pragma unroll
                for (int j = 0; j < 7; j++) {
                    int n = lane + j * 32;
                    float s = (n < NREG) ? __ldcg(&g_sc[b * NREG + n]) : -3.4e38f;
                    ev[j] = s;
                    mx = fmaxf(mx, s);
                }
                mx = allmax(mx);
                float sum = 0.f;
                #pragma unroll
                for (int j = 0; j < 7; j++) {
                    int n = lane + j * 32;
                    float e = (n < NREG) ? expf(ev[j] - mx) : 0.f;
                    ev[j] = e;
                    sum += e;
                }
                sum = allsum(sum);
                float inv = 1.f / sum;
                float* ab = abuf + w * 224;
                #pragma unroll
                for (int j = 0; j < 7; j++) {
                    int n = lane + j * 32;
                    if (n < NREG) ab[n] = ev[j] * inv;
                }
                __syncwarp();
                const float* fp = F + (size_t)b * NREG * EMB + ec * 32 + lane;
                float a0 = 0.f, a1 = 0.f, a2 = 0.f, a3 = 0.f;
                #pragma unroll 4
                for (int n = 0; n < 196; n += 4) {
                    a0 = fmaf(ab[n],     fp[(size_t)n * 512],       a0);
                    a1 = fmaf(ab[n + 1], fp[(size_t)(n + 1) * 512], a1);
                    a2 = fmaf(ab[n + 2], fp[(size_t)(n + 2) * 512], a2);
                    a3 = fmaf(ab[n + 3], fp[(size_t)(n + 3) * 512], a3);
                }
                g_ctx[b * 512 + ec * 32 + lane] = (a0 + a1) + (a2 + a3);
            }
        }
        gbar(ep);
        // ======== Phase C: stage ctxT; gates = ctx@M^T + h@Whh^T + pre2 + bias; update
        {
            const float4* cg = (const float4*)g_ctx;
            for (int i = tid; i < 4096; i += 256) {
                float4 v = __ldcg(cg + i);
                act4[(128 + (i & 127)) * 33 + (i >> 7)] = v;
            }
            __syncthreads();
            if (hasq) {
                const float4* wsM0 = (const float4*)(ws2 + (size_t)((w * 2 + 0) * 2 + 0) * 512);
                const float4* wsM1 = (const float4*)(ws2 + (size_t)((w * 2 + 0) * 2 + 1) * 512);
                const float4* wsH0 = (const float4*)(ws2 + (size_t)((w * 2 + 1) * 2 + 0) * 512);
                const float4* wsH1 = (const float4*)(ws2 + (size_t)((w * 2 + 1) * 2 + 1) * 512);
                const float4* ac = act4 + 128 * 33 + lane;
                const float4* ah = act4 + lane;
                float2 ifM = make_float2(0.f, 0.f), goM = make_float2(0.f, 0.f);
                float2 ifH = make_float2(0.f, 0.f), goH = make_float2(0.f, 0.f);
                #pragma unroll 4
                for (int k4 = 0; k4 < 128; k4++) {
                    float4 x = ac[k4 * 33];
                    float4 wa = wsM0[2 * k4], wb = wsM0[2 * k4 + 1];
                    ffma2(ifM, make_float2(wa.x, wa.y), make_float2(x.x, x.x));
                    ffma2(ifM, make_float2(wa.z, wa.w), make_float2(x.y, x.y));
                    ffma2(ifM, make_float2(wb.x, wb.y), make_float2(x.z, x.z));
                    ffma2(ifM, make_float2(wb.z, wb.w), make_float2(x.w, x.w));
                    wa = wsM1[2 * k4]; wb = wsM1[2 * k4 + 1];
                    ffma2(goM, make_float2(wa.x, wa.y), make_float2(x.x, x.x));
                    ffma2(goM, make_float2(wa.z, wa.w), make_float2(x.y, x.y));
                    ffma2(goM, make_float2(wb.x, wb.y), make_float2(x.z, x.z));
                    ffma2(goM, make_float2(wb.z, wb.w), make_float2(x.w, x.w));
                    float4 y = ah[k4 * 33];
                    wa = wsH0[2 * k4]; wb = wsH0[2 * k4 + 1];
                    ffma2(ifH, make_float2(wa.x, wa.y), make_float2(y.x, y.x));
                    ffma2(ifH, make_float2(wa.z, wa.w), make_float2(y.y, y.y));
                    ffma2(ifH, make_float2(wb.x, wb.y), make_float2(y.z, y.z));
                    ffma2(ifH, make_float2(wb.z, wb.w), make_float2(y.w, y.w));
                    wa = wsH1[2 * k4]; wb = wsH1[2 * k4 + 1];
                    ffma2(goH, make_float2(wa.x, wa.y), make_float2(y.x, y.x));
                    ffma2(goH, make_float2(wa.z, wa.w), make_float2(y.y, y.y));
                    ffma2(goH, make_float2(wb.x, wb.y), make_float2(y.z, y.z));
                    ffma2(goH, make_float2(wb.z, wb.w), make_float2(y.w, y.w));
                }
                size_t pb = ((size_t)(t * 2048 + q)) * 32 + lane;
                float pi = g_pre2T[pb];
                float pf = g_pre2T[pb + 512 * 32];
                float pg = g_pre2T[pb + 1024 * 32];
                float po = g_pre2T[pb + 1536 * 32];
                float gi = ifM.x + ifH.x + pi + biasq[0];
                float gf = ifM.y + ifH.y + pf + biasq[1];
                float gg = goM.x + goH.x + pg + biasq[2];
                float go = goM.y + goH.y + po + biasq[3];
                float si = 1.f / (1.f + expf(-gi));
                float sf = 1.f / (1.f + expf(-gf));
                float so = 1.f / (1.f + expf(-go));
                c_l = sf * c_l + si * tanhf(gg);
                float h2 = so * tanhf(c_l);
                g_h[lane * 512 + q] = h2;
                g_H[(size_t)((lane << 6) + t) * 512 + q] = h2;
            }
        }
        gbar(ep);
    }
}

// ---------------- launch ----------------
extern "C" void kernel_launch(void* const* d_in, const int* in_sizes, int n_in,
                              void* d_out, int out_size) {
    const float* features = (const float*)d_in[0];
    const int*   captions = (const int*)  d_in[1];
    const float* embW     = (const float*)d_in[2];
    const float* ihW      = (const float*)d_in[3];
    const float* ihb      = (const float*)d_in[4];
    const float* icW      = (const float*)d_in[5];
    const float* icb      = (const float*)d_in[6];
    const float* rW       = (const float*)d_in[7];
    const float* rb       = (const float*)d_in[8];
    const float* Wih      = (const float*)d_in[9];
    const float* Whh      = (const float*)d_in[10];
    const float* bih      = (const float*)d_in[11];
    const float* bhh      = (const float*)d_in[12];
    const float* oW       = (const float*)d_in[13];
    const float* ob       = (const float*)d_in[14];
    float* out = (float*)d_out;

    static int inited = 0;
    static float *pEmb, *pXe, *pM, *pRWT, *pPre, *pH;
    if (!inited) {
        cudaFuncSetAttribute(k_rec, cudaFuncAttributeMaxDynamicSharedMemorySize, 204288);
        cudaGetSymbolAddress((void**)&pEmb, g_emb);
        cudaGetSymbolAddress((void**)&pXe,  g_xe);
        cudaGetSymbolAddress((void**)&pM,   g_M);
        cudaGetSymbolAddress((void**)&pRWT, g_rWT);
        cudaGetSymbolAddress((void**)&pPre, g_pre2T);
        cudaGetSymbolAddress((void**)&pH,   g_H);
        inited = 1;
    }

    k_embed<<<2048, 512>>>(captions, embW);               // + barrier reset
    k_trans<<<dim3(16, 16), dim3(32, 8)>>>(rW);           // rWT = rW1^T
    k_fmean<<<32, 256>>>(features);
    k_init <<<4096, 256>>>(ihW, ihb, icW, icb);
    // one-time algebraic hoists
    k_gemm<<<dim3(4, 16), 256>>>(pEmb, 512, rW + 512, 1024, rb, pXe, 512, 0);   // xe
    k_gemm<<<dim3(4, 16), 256>>>(Wih, 512, pRWT, 512, nullptr, pM, 512, 0);     // M = Wih@rW1
    k_gemm<<<dim3(16, 16), 256>>>(pXe, 512, Wih, 512, nullptr, pPre, 0, 1);     // pre2T
    // recurrence
    k_rec<<<NCTA, 256, 204288>>>(features, Whh, bih, bhh);
    // batched output projection
    k_gemm<<<dim3(250, 16), 256>>>(pH, 512, oW, 512, ob, out, VOC, 0);
}

// round 10
// speedup vs baseline: 2.6346x; 2.1773x over previous
#include <cuda_runtime.h>
#include <math.h>

#define BB   32
#define SEQ  64
#define EMB  512
#define HID  512
#define NREG 196
#define VOC  32000
#define SQRTE 22.62741699796952f
#define NCTA 148

// ---------------- device scratch (static; no runtime alloc) ----------------
__device__ float g_emb[BB * SEQ * EMB];       // 4 MB  [m][e], m = b*64+t
__device__ float g_fmean[BB * EMB];
__device__ float g_h[BB * HID];
__device__ float g_c[BB * HID];
__device__ float g_sc[BB * NREG];
__device__ float g_ctx[BB * EMB];
__device__ float g_xe[BB * SEQ * EMB];        // 4 MB  emb-half of reshape (+rb)
__device__ float g_H[BB * SEQ * HID];         // 4 MB  row m = b*64+t
__device__ float g_rWT[EMB * EMB];            // 1 MB  rW[:, :512] transposed
__device__ float g_M[4 * HID * EMB];          // 4 MB  M = Wih @ rW1
__device__ float g_pre2T[SEQ * 4 * HID * BB]; // 16 MB pre2T[t][r][b]
__device__ unsigned g_arrive;

// ---------------- helpers ----------------
__device__ __forceinline__ float allsum(float v) {
    #pragma unroll
    for (int o = 16; o > 0; o >>= 1) v += __shfl_xor_sync(0xffffffffu, v, o);
    return v;
}
__device__ __forceinline__ float allmax(float v) {
    #pragma unroll
    for (int o = 16; o > 0; o >>= 1) v = fmaxf(v, __shfl_xor_sync(0xffffffffu, v, o));
    return v;
}
// packed dual-FMA (FFMA2) — only reachable via PTX fma.rn.f32x2 on sm_10x
__device__ __forceinline__ void ffma2(float2& d, const float2& a, const float2& b) {
    asm("fma.rn.f32x2 %0, %1, %2, %0;"
        : "+l"(*reinterpret_cast<unsigned long long*>(&d))
        : "l"(*reinterpret_cast<const unsigned long long*>(&a)),
          "l"(*reinterpret_cast<const unsigned long long*>(&b)));
}
__device__ __forceinline__ void dotacc(float2& acc, const float4& w, const float4& v) {
    float2 a0 = make_float2(w.x, w.y), b0 = make_float2(v.x, v.y);
    ffma2(acc, a0, b0);
    float2 a1 = make_float2(w.z, w.w), b1 = make_float2(v.z, v.w);
    ffma2(acc, a1, b1);
}
__device__ __forceinline__ unsigned f2tf32(float x) {
    unsigned u;
    asm("cvt.rna.tf32.f32 %0, %1;" : "=r"(u) : "f"(x));
    return u;
}
__device__ __forceinline__ void mma_tf32(float* d, const unsigned* a, const unsigned* b) {
    asm("mma.sync.aligned.m16n8k8.row.col.f32.tf32.tf32.f32 "
        "{%0,%1,%2,%3}, {%4,%5,%6,%7}, {%8,%9}, {%0,%1,%2,%3};"
        : "+f"(d[0]), "+f"(d[1]), "+f"(d[2]), "+f"(d[3])
        : "r"(a[0]), "r"(a[1]), "r"(a[2]), "r"(a[3]), "r"(b[0]), "r"(b[1]));
}

// grid-wide software barrier: requires grid == NCTA <= #SMs (all co-resident)
__device__ __forceinline__ void gbar(unsigned& ep) {
    ep += NCTA;
    __threadfence();
    __syncthreads();
    if (threadIdx.x == 0) {
        atomicAdd(&g_arrive, 1u);
        volatile unsigned* p = &g_arrive;
        while (*p < ep) { }
        __threadfence();
    }
    __syncthreads();
}

// ---------------- one-time prep ----------------
__global__ void k_embed(const int* __restrict__ caps, const float* __restrict__ embW) {
    if (blockIdx.x == 0 && threadIdx.x == 0) g_arrive = 0;   // barrier reset each launch
    int idx = blockIdx.x * 512 + threadIdx.x;
    int bt = idx >> 9, e = idx & 511;
    int c = caps[bt];
    g_emb[idx] = embW[c * 512 + e] * SQRTE;
}

__global__ void k_trans(const float* __restrict__ rW) {   // g_rWT[k][j] = rW[j][k], k<512
    __shared__ float tile[32][33];
    int bk = blockIdx.x * 32, bj = blockIdx.y * 32;
    int tx = threadIdx.x, ty0 = threadIdx.y;               // 32 x 8
    #pragma unroll
    for (int i = 0; i < 4; i++) {
        int ty = ty0 + i * 8;
        tile[ty][tx] = rW[(size_t)(bj + ty) * 1024 + bk + tx];
    }
    __syncthreads();
    #pragma unroll
    for (int i = 0; i < 4; i++) {
        int ty = ty0 + i * 8;
        g_rWT[(size_t)(bk + ty) * 512 + bj + tx] = tile[tx][ty];
    }
}

__global__ void k_fmean(const float* __restrict__ F) {
    int b = blockIdx.x;
    for (int e = threadIdx.x; e < EMB; e += 256) {
        const float* p = F + (size_t)b * NREG * EMB + e;
        float s = 0.f;
        #pragma unroll 4
        for (int n = 0; n < NREG; n++) s += p[(size_t)n * EMB];
        g_fmean[b * EMB + e] = s * (1.0f / NREG);
    }
}

__global__ void k_init(const float* __restrict__ hW, const float* __restrict__ hb,
                       const float* __restrict__ cW, const float* __restrict__ cb) {
    int w = (blockIdx.x << 3) + (threadIdx.x >> 5);
    int lane = threadIdx.x & 31;
    int which = w >> 14;
    int bj = w & 16383;
    int b = bj >> 9, j = bj & 511;
    const float4* Wp = (const float4*)((which ? cW : hW) + (size_t)j * EMB);
    const float4* fp = (const float4*)(g_fmean + b * EMB);
    float s = 0.f;
    #pragma unroll
    for (int i = 0; i < 4; i++) {
        int id = lane + i * 32;
        float4 a = Wp[id], x = fp[id];
        s += a.x * x.x + a.y * x.y + a.z * x.z + a.w * x.w;
    }
    s = allsum(s);
    if (lane == 0) {
        if (which) g_c[b * HID + j] = s + cb[j];
        else       g_h[b * HID + j] = s + hb[j];
    }
}

// ---------------- generic 128x128 FFMA2 GEMM (fp32, used for hoists) ----------
// K = 512 always. transout=1 writes pre2T layout [(m&63)*2048+v]*32 + (m>>6).
__global__ void k_gemm(const float* __restrict__ A, int lda,
                       const float* __restrict__ Bm, int ldb,
                       const float* __restrict__ bias,
                       float* __restrict__ C, int ldc, int transout) {
    __shared__ float2 As2[16 * 129];
    __shared__ float  Bs [16 * 130];
    int tid = threadIdx.x;
    int tx = tid & 15, ty = tid >> 4;
    int vt = blockIdx.x * 128;
    int mt = blockIdx.y * 128;

    float2 acc[8][4];
    #pragma unroll
    for (int i = 0; i < 8; i++)
        #pragma unroll
        for (int q = 0; q < 4; q++) acc[i][q] = make_float2(0.f, 0.f);

    for (int kc = 0; kc < 32; kc++) {
        __syncthreads();
        #pragma unroll
        for (int i = 0; i < 2; i++) {
            int f4 = tid + i * 256;
            int m = f4 >> 2, kk = f4 & 3;
            float4 a = *(const float4*)(A + (size_t)(mt + m) * lda + kc * 16 + kk * 4);
            int kb = kk * 4;
            As2[(kb + 0) * 129 + m] = make_float2(a.x, a.x);
            As2[(kb + 1) * 129 + m] = make_float2(a.y, a.y);
            As2[(kb + 2) * 129 + m] = make_float2(a.z, a.z);
            As2[(kb + 3) * 129 + m] = make_float2(a.w, a.w);
            float4 bv = *(const float4*)(Bm + (size_t)(vt + m) * ldb + kc * 16 + kk * 4);
            Bs[(kb + 0) * 130 + m] = bv.x;
            Bs[(kb + 1) * 130 + m] = bv.y;
            Bs[(kb + 2) * 130 + m] = bv.z;
            Bs[(kb + 3) * 130 + m] = bv.w;
        }
        __syncthreads();
        #pragma unroll
        for (int k = 0; k < 16; k++) {
            float2 b2[4];
            #pragma unroll
            for (int q = 0; q < 4; q++)
                b2[q] = *(const float2*)&Bs[k * 130 + 2 * tx + 32 * q];
            #pragma unroll
            for (int i = 0; i < 8; i++) {
                float2 a2 = As2[k * 129 + ty * 8 + i];
                #pragma unroll
                for (int q = 0; q < 4; q++) ffma2(acc[i][q], a2, b2[q]);
            }
        }
    }
    #pragma unroll
    for (int q = 0; q < 4; q++) {
        int v = vt + 2 * tx + 32 * q;
        float2 bb = bias ? *(const float2*)(bias + v) : make_float2(0.f, 0.f);
        #pragma unroll
        for (int i = 0; i < 8; i++) {
            int m = mt + ty * 8 + i;
            float2 r = make_float2(acc[i][q].x + bb.x, acc[i][q].y + bb.y);
            if (!transout) {
                *(float2*)(C + (size_t)m * ldc + v) = r;
            } else {
                size_t base = ((size_t)((m & 63) * 2048 + v)) * 32 + (m >> 6);
                C[base]      = r.x;
                C[base + 32] = r.y;
            }
        }
    }
}

// ---------------- tf32 tensor-core output GEMM: out = H @ oW^T + ob ----------
// C = [2048 x 32000], K=512. Tile 128x128, BK=32, 8 warps (4m x 2n), warp 32x64.
__global__ void __launch_bounds__(256, 1)
k_out_tc(const float* __restrict__ Wt, const float* __restrict__ ob,
         float* __restrict__ out) {
    __shared__ unsigned As[128 * 36];
    __shared__ unsigned Bsm[128 * 36];
    int tid = threadIdx.x, lane = tid & 31, wid = tid >> 5;
    int wm = wid & 3, wn = wid >> 2;
    int vt = blockIdx.x * 128, mt = blockIdx.y * 128;

    float d[2][8][4];
    #pragma unroll
    for (int mi = 0; mi < 2; mi++)
        #pragma unroll
        for (int nj = 0; nj < 8; nj++)
            #pragma unroll
            for (int e = 0; e < 4; e++) d[mi][nj][e] = 0.f;

    for (int kc = 0; kc < 16; kc++) {
        __syncthreads();
        #pragma unroll
        for (int i = 0; i < 4; i++) {
            int row = (tid >> 3) + i * 32;
            int col = (tid & 7) * 4;
            float4 a = *(const float4*)(g_H + (size_t)(mt + row) * 512 + kc * 32 + col);
            unsigned* pa = &As[row * 36 + col];
            pa[0] = f2tf32(a.x); pa[1] = f2tf32(a.y);
            pa[2] = f2tf32(a.z); pa[3] = f2tf32(a.w);
            float4 b = *(const float4*)(Wt + (size_t)(vt + row) * 512 + kc * 32 + col);
            unsigned* pb = &Bsm[row * 36 + col];
            pb[0] = f2tf32(b.x); pb[1] = f2tf32(b.y);
            pb[2] = f2tf32(b.z); pb[3] = f2tf32(b.w);
        }
        __syncthreads();
        int c = lane & 3, r = lane >> 2;
        #pragma unroll
        for (int k8 = 0; k8 < 4; k8++) {
            int k0 = k8 * 8;
            unsigned af[2][4];
            #pragma unroll
            for (int mi = 0; mi < 2; mi++) {
                int base = (wm * 32 + mi * 16 + r) * 36 + k0 + c;
                af[mi][0] = As[base];
                af[mi][1] = As[base + 8 * 36];
                af[mi][2] = As[base + 4];
                af[mi][3] = As[base + 8 * 36 + 4];
            }
            unsigned bf[8][2];
            #pragma unroll
            for (int nj = 0; nj < 8; nj++) {
                int base = (wn * 64 + nj * 8 + r) * 36 + k0 + c;
                bf[nj][0] = Bsm[base];
                bf[nj][1] = Bsm[base + 4];
            }
            #pragma unroll
            for (int mi = 0; mi < 2; mi++)
                #pragma unroll
                for (int nj = 0; nj < 8; nj++)
                    mma_tf32(d[mi][nj], af[mi], bf[nj]);
        }
    }
    int c = lane & 3, r = lane >> 2;
    #pragma unroll
    for (int mi = 0; mi < 2; mi++) {
        #pragma unroll
        for (int nj = 0; nj < 8; nj++) {
            int m0 = mt + wm * 32 + mi * 16 + r;
            int v0 = vt + wn * 64 + nj * 8 + 2 * c;
            float2 bb = *(const float2*)(ob + v0);
            float2 r0 = make_float2(d[mi][nj][0] + bb.x, d[mi][nj][1] + bb.y);
            float2 r1 = make_float2(d[mi][nj][2] + bb.x, d[mi][nj][3] + bb.y);
            *(float2*)(out + (size_t)m0 * VOC + v0) = r0;
            *(float2*)(out + (size_t)(m0 + 8) * VOC + v0) = r1;
        }
    }
}

// ---------------- persistent fused recurrence ----------------
// grid = 148 CTAs x 256 thr. dyn smem 212480 B:
//   act4[8448] float4 (hT rows 0..127, ctxT 128..255; [k4][b], pad 33)  135168
//   ws  [16384] float (per-unit gate rows: [u][src][gate][512])          65536
//   abuf[8*224] float (per-warp attention weights)                        7168
//   redC[512]  float2 (phase C k-split partials)                          4096
//   redB[128]  float  (phase B n-split partials)                           512
__global__ void __launch_bounds__(256, 1)
k_rec(const float* __restrict__ F, const float* __restrict__ Whh,
      const float* __restrict__ bih, const float* __restrict__ bhh) {
    extern __shared__ float4 smem4[];
    float4* act4 = smem4;
    float*  ws   = (float*)(smem4 + 8448);
    float*  abuf = ws + 16384;
    float2* redC = (float2*)(abuf + 1792);
    float*  redB = (float*)(redC + 512);
    const int tid = threadIdx.x, lane = tid & 31, w = tid >> 5;
    const int cta = blockIdx.x;
    unsigned ep = 0;

    const int u  = w & 3;          // unit slot within CTA
    const int kh = w >> 2;         // k-half (0: k<256, 1: k>=256)
    const int q  = cta + NCTA * u; // hidden unit owned by slot u
    const bool uvalid = (q < 512);

    // stage gate weights once: warp w stages src kh (0=M, 1=Whh) for unit u
    if (uvalid) {
        const float* src = kh ? Whh : g_M;
        #pragma unroll
        for (int g = 0; g < 4; g++) {
            const float* rp = src + (size_t)(q + g * 512) * 512;
            float* dst = ws + u * 4096 + kh * 2048 + g * 512;
            for (int j = lane; j < 512; j += 32) dst[j] = rp[j];
        }
    }
    float c_l = 0.f;
    float biasq[4] = {0.f, 0.f, 0.f, 0.f};
    if (uvalid && kh == 0) {
        c_l = __ldcg(&g_c[lane * 512 + q]);
        #pragma unroll
        for (int g = 0; g < 4; g++) biasq[g] = bih[q + g * 512] + bhh[q + g * 512];
    }
    __syncthreads();

    const float4* F4 = (const float4*)F;
    const int gw = cta * 8 + w;

    for (int t = 0; t < SEQ; t++) {
        // ======== Phase A: stage hT; scores over all 8 warps ========
        {
            const float4* hg = (const float4*)g_h;
            for (int i = tid; i < 4096; i += 256) {
                float4 v = __ldcg(hg + i);
                act4[(i & 127) * 33 + (i >> 7)] = v;          // [k4][b]
            }
            __syncthreads();
            for (int dd = gw; dd < BB * NREG; dd += 1184) {
                int b = dd / NREG;
                const float4* fr = F4 + (size_t)dd * 128;
                float2 a = make_float2(0.f, 0.f);
                #pragma unroll
                for (int i = 0; i < 4; i++)
                    dotacc(a, fr[lane + 32 * i], act4[(lane + 32 * i) * 33 + b]);
                float s = allsum(a.x + a.y);
                if (lane == 0) g_sc[dd] = s;
            }
        }
        gbar(ep);
        // ======== Phase B: softmax (redundant per warp pair) + context, n-split
        {
            float csum = 0.f;
            int b = 0, ec = 0;
            const bool bvalid = uvalid;                       // tb = q < 512
            if (bvalid) {
                int tb = q;
                b = tb >> 4; ec = tb & 15;
                float ev[7];
                float mx = -3.4e38f;
                #pragma unroll
                for (int j = 0; j < 7; j++) {
                    int n = lane + j * 32;
                    float s = (n < NREG) ? __ldcg(&g_sc[b * NREG + n]) : -3.4e38f;
                    ev[j] = s;
                    mx = fmaxf(mx, s);
                }
                mx = allmax(mx);
                float sum = 0.f;
                #pragma unroll
                for (int j = 0; j < 7; j++) {
                    int n = lane + j * 32;
                    float e = (n < NREG) ? expf(ev[j] - mx) : 0.f;
                    ev[j] = e;
                    sum += e;
                }
                sum = allsum(sum);
                float inv = 1.f / sum;
                float* ab = abuf + w * 224;
                #pragma unroll
                for (int j = 0; j < 7; j++) {
                    int n = lane + j * 32;
                    if (n < NREG) ab[n] = ev[j] * inv;
                }
                __syncwarp();
                const float* fp = F + (size_t)b * NREG * EMB + ec * 32 + lane;
                int n0 = kh ? 96 : 0, n1 = kh ? 196 : 96;
                float a0 = 0.f, a1 = 0.f, a2 = 0.f, a3 = 0.f;
                for (int n = n0; n < n1; n += 4) {
                    a0 = fmaf(ab[n],     fp[(size_t)n * 512],       a0);
                    a1 = fmaf(ab[n + 1], fp[(size_t)(n + 1) * 512], a1);
                    a2 = fmaf(ab[n + 2], fp[(size_t)(n + 2) * 512], a2);
                    a3 = fmaf(ab[n + 3], fp[(size_t)(n + 3) * 512], a3);
                }
                csum = (a0 + a1) + (a2 + a3);
                if (kh) redB[u * 32 + lane] = csum;
            }
            __syncthreads();
            if (bvalid && kh == 0)
                g_ctx[b * 512 + ec * 32 + lane] = csum + redB[u * 32 + lane];
        }
        gbar(ep);
        // ======== Phase C: stage ctxT; gates = ctx@M^T + h@Whh^T + pre2 + bias;
        //          k-split across warp pairs; fused LSTM update ========
        {
            const float4* cg = (const float4*)g_ctx;
            for (int i = tid; i < 4096; i += 256) {
                float4 v = __ldcg(cg + i);
                act4[(128 + (i & 127)) * 33 + (i >> 7)] = v;
            }
            __syncthreads();
            float2 acc[4];
            #pragma unroll
            for (int g = 0; g < 4; g++) acc[g] = make_float2(0.f, 0.f);
            if (uvalid) {
                const float4* wM0 = (const float4*)(ws + u * 4096);
                const float4* wM1 = (const float4*)(ws + u * 4096 + 512);
                const float4* wM2 = (const float4*)(ws + u * 4096 + 1024);
                const float4* wM3 = (const float4*)(ws + u * 4096 + 1536);
                const float4* wH0 = (const float4*)(ws + u * 4096 + 2048);
                const float4* wH1 = (const float4*)(ws + u * 4096 + 2560);
                const float4* wH2 = (const float4*)(ws + u * 4096 + 3072);
                const float4* wH3 = (const float4*)(ws + u * 4096 + 3584);
                const int ko = kh * 64;
                const float4* pc = act4 + (size_t)(128 + ko) * 33 + lane;
                const float4* ph = act4 + (size_t)ko * 33 + lane;
                #pragma unroll 4
                for (int k4 = 0; k4 < 64; k4++) {
                    float4 x = pc[k4 * 33];
                    float4 y = ph[k4 * 33];
                    float4 m0 = wM0[ko + k4], m1 = wM1[ko + k4];
                    float4 m2 = wM2[ko + k4], m3 = wM3[ko + k4];
                    ffma2(acc[0], make_float2(m0.x, m0.y), make_float2(x.x, x.y));
                    ffma2(acc[0], make_float2(m0.z, m0.w), make_float2(x.z, x.w));
                    ffma2(acc[1], make_float2(m1.x, m1.y), make_float2(x.x, x.y));
                    ffma2(acc[1], make_float2(m1.z, m1.w), make_float2(x.z, x.w));
                    ffma2(acc[2], make_float2(m2.x, m2.y), make_float2(x.x, x.y));
                    ffma2(acc[2], make_float2(m2.z, m2.w), make_float2(x.z, x.w));
                    ffma2(acc[3], make_float2(m3.x, m3.y), make_float2(x.x, x.y));
                    ffma2(acc[3], make_float2(m3.z, m3.w), make_float2(x.z, x.w));
                    float4 h0 = wH0[ko + k4], h1 = wH1[ko + k4];
                    float4 h2 = wH2[ko + k4], h3 = wH3[ko + k4];
                    ffma2(acc[0], make_float2(h0.x, h0.y), make_float2(y.x, y.y));
                    ffma2(acc[0], make_float2(h0.z, h0.w), make_float2(y.z, y.w));
                    ffma2(acc[1], make_float2(h1.x, h1.y), make_float2(y.x, y.y));
                    ffma2(acc[1], make_float2(h1.z, h1.w), make_float2(y.z, y.w));
                    ffma2(acc[2], make_float2(h2.x, h2.y), make_float2(y.x, y.y));
                    ffma2(acc[2], make_float2(h2.z, h2.w), make_float2(y.z, y.w));
                    ffma2(acc[3], make_float2(h3.x, h3.y), make_float2(y.x, y.y));
                    ffma2(acc[3], make_float2(h3.z, h3.w), make_float2(y.z, y.w));
                }
                if (kh) {
                    #pragma unroll
                    for (int g = 0; g < 4; g++)
                        redC[(u * 32 + lane) * 4 + g] = acc[g];
                }
            }
            __syncthreads();
            if (uvalid && kh == 0) {
                float gate[4];
                size_t pb = ((size_t)(t * 2048 + q)) * 32 + lane;
                #pragma unroll
                for (int g = 0; g < 4; g++) {
                    float2 pr = redC[(u * 32 + lane) * 4 + g];
                    gate[g] = (acc[g].x + acc[g].y) + (pr.x + pr.y)
                            + g_pre2T[pb + (size_t)g * 512 * 32] + biasq[g];
                }
                float si = 1.f / (1.f + expf(-gate[0]));
                float sf = 1.f / (1.f + expf(-gate[1]));
                float so = 1.f / (1.f + expf(-gate[3]));
                c_l = sf * c_l + si * tanhf(gate[2]);
                float h2v = so * tanhf(c_l);
                g_h[lane * 512 + q] = h2v;
                g_H[(size_t)((lane << 6) + t) * 512 + q] = h2v;
            }
        }
        gbar(ep);
    }
}

// ---------------- launch ----------------
extern "C" void kernel_launch(void* const* d_in, const int* in_sizes, int n_in,
                              void* d_out, int out_size) {
    const float* features = (const float*)d_in[0];
    const int*   captions = (const int*)  d_in[1];
    const float* embW     = (const float*)d_in[2];
    const float* ihW      = (const float*)d_in[3];
    const float* ihb      = (const float*)d_in[4];
    const float* icW      = (const float*)d_in[5];
    const float* icb      = (const float*)d_in[6];
    const float* rW       = (const float*)d_in[7];
    const float* rb       = (const float*)d_in[8];
    const float* Wih      = (const float*)d_in[9];
    const float* Whh      = (const float*)d_in[10];
    const float* bih      = (const float*)d_in[11];
    const float* bhh      = (const float*)d_in[12];
    const float* oW       = (const float*)d_in[13];
    const float* ob       = (const float*)d_in[14];
    float* out = (float*)d_out;

    static int inited = 0;
    static float *pEmb, *pXe, *pM, *pRWT, *pPre;
    if (!inited) {
        cudaFuncSetAttribute(k_rec, cudaFuncAttributeMaxDynamicSharedMemorySize, 212480);
        cudaGetSymbolAddress((void**)&pEmb, g_emb);
        cudaGetSymbolAddress((void**)&pXe,  g_xe);
        cudaGetSymbolAddress((void**)&pM,   g_M);
        cudaGetSymbolAddress((void**)&pRWT, g_rWT);
        cudaGetSymbolAddress((void**)&pPre, g_pre2T);
        inited = 1;
    }

    k_embed<<<2048, 512>>>(captions, embW);               // + barrier reset
    k_trans<<<dim3(16, 16), dim3(32, 8)>>>(rW);           // rWT = rW1^T
    k_fmean<<<32, 256>>>(features);
    k_init <<<4096, 256>>>(ihW, ihb, icW, icb);
    // one-time algebraic hoists (fp32)
    k_gemm<<<dim3(4, 16), 256>>>(pEmb, 512, rW + 512, 1024, rb, pXe, 512, 0);   // xe
    k_gemm<<<dim3(4, 16), 256>>>(Wih, 512, pRWT, 512, nullptr, pM, 512, 0);     // M = Wih@rW1
    k_gemm<<<dim3(16, 16), 256>>>(pXe, 512, Wih, 512, nullptr, pPre, 0, 1);     // pre2T
    // recurrence
    k_rec<<<NCTA, 256, 212480>>>(features, Whh, bih, bhh);
    // batched output projection (tf32 tensor cores)
    k_out_tc<<<dim3(250, 16), 256>>>(oW, ob, out);
}

// round 11
// speedup vs baseline: 3.0270x; 1.1489x over previous
#include <cuda_runtime.h>
#include <math.h>

#define BB   32
#define SEQ  64
#define EMB  512
#define HID  512
#define NREG 196
#define VOC  32000
#define SQRTE 22.62741699796952f
#define NCTA 148

// ---------------- device scratch (static; no runtime alloc) ----------------
__device__ float    g_emb[BB * SEQ * EMB];       // 4 MB  [m][e], m = b*64+t
__device__ float    g_fmean[BB * EMB];
__device__ float    g_h[BB * HID];
__device__ float    g_c[BB * HID];
__device__ float    g_sc[BB * NREG];
__device__ float    g_ctx[BB * EMB];
__device__ float    g_xe[BB * SEQ * EMB];        // 4 MB  emb-half of reshape (+rb)
__device__ unsigned g_Ht[BB * SEQ * HID];        // 4 MB  tf32 bits of H, row m=b*64+t
__device__ float    g_rWT[EMB * EMB];            // 1 MB  rW[:, :512] transposed
__device__ float    g_M[4 * HID * EMB];          // 4 MB  M = Wih @ rW1
__device__ float    g_pre2T[SEQ * 4 * HID * BB]; // 16 MB pre2T[t][r][b]
__device__ unsigned g_oWt[VOC * EMB];            // 65.5 MB tf32 bits of out_W
__device__ unsigned g_arrive;

// ---------------- helpers ----------------
__device__ __forceinline__ float allsum(float v) {
    #pragma unroll
    for (int o = 16; o > 0; o >>= 1) v += __shfl_xor_sync(0xffffffffu, v, o);
    return v;
}
__device__ __forceinline__ float allmax(float v) {
    #pragma unroll
    for (int o = 16; o > 0; o >>= 1) v = fmaxf(v, __shfl_xor_sync(0xffffffffu, v, o));
    return v;
}
// packed dual-FMA (FFMA2) — only reachable via PTX fma.rn.f32x2 on sm_10x
__device__ __forceinline__ void ffma2(float2& d, const float2& a, const float2& b) {
    asm("fma.rn.f32x2 %0, %1, %2, %0;"
        : "+l"(*reinterpret_cast<unsigned long long*>(&d))
        : "l"(*reinterpret_cast<const unsigned long long*>(&a)),
          "l"(*reinterpret_cast<const unsigned long long*>(&b)));
}
__device__ __forceinline__ void dotacc(float2& acc, const float4& w, const float4& v) {
    float2 a0 = make_float2(w.x, w.y), b0 = make_float2(v.x, v.y);
    ffma2(acc, a0, b0);
    float2 a1 = make_float2(w.z, w.w), b1 = make_float2(v.z, v.w);
    ffma2(acc, a1, b1);
}
__device__ __forceinline__ unsigned f2tf32(float x) {
    unsigned u;
    asm("cvt.rna.tf32.f32 %0, %1;" : "=r"(u) : "f"(x));
    return u;
}
__device__ __forceinline__ void mma_tf32(float* d, const unsigned* a, const unsigned* b) {
    asm("mma.sync.aligned.m16n8k8.row.col.f32.tf32.tf32.f32 "
        "{%0,%1,%2,%3}, {%4,%5,%6,%7}, {%8,%9}, {%0,%1,%2,%3};"
        : "+f"(d[0]), "+f"(d[1]), "+f"(d[2]), "+f"(d[3])
        : "r"(a[0]), "r"(a[1]), "r"(a[2]), "r"(a[3]), "r"(b[0]), "r"(b[1]));
}
__device__ __forceinline__ unsigned smem_u32(const void* p) {
    unsigned a;
    asm("{ .reg .u64 t; cvta.to.shared.u64 t, %1; cvt.u32.u64 %0, t; }"
        : "=r"(a) : "l"(p));
    return a;
}
__device__ __forceinline__ void cpasync16(unsigned s, const void* g) {
    asm volatile("cp.async.cg.shared.global [%0], [%1], 16;"
                 :: "r"(s), "l"((unsigned long long)__cvta_generic_to_global(g)));
}

// grid-wide software barrier: requires grid == NCTA <= #SMs (all co-resident)
__device__ __forceinline__ void gbar(unsigned& ep) {
    ep += NCTA;
    __threadfence();
    __syncthreads();
    if (threadIdx.x == 0) {
        atomicAdd(&g_arrive, 1u);
        volatile unsigned* p = &g_arrive;
        while (*p < ep) { }
        __threadfence();
    }
    __syncthreads();
}

// ---------------- fused one-time prep: embed + rW1 transpose + fmean ----------
__global__ void k_prep(const int* __restrict__ caps, const float* __restrict__ embW,
                       const float* __restrict__ rW, const float* __restrict__ F) {
    __shared__ float tile[32][33];
    int bid = blockIdx.x, tid = threadIdx.x;
    if (bid == 0 && tid == 0) g_arrive = 0;              // barrier reset each launch
    if (bid < 4096) {                                     // embeddings
        int idx = bid * 256 + tid;
        int bt = idx >> 9, e = idx & 511;
        g_emb[idx] = embW[caps[bt] * 512 + e] * SQRTE;
    } else if (bid < 4352) {                              // rWT = rW[:, :512]^T
        int tI = bid - 4096;
        int bk = (tI & 15) * 32, bj = (tI >> 4) * 32;
        int tx = tid & 31, ty0 = tid >> 5;
        #pragma unroll
        for (int i = 0; i < 4; i++) {
            int ty = ty0 + i * 8;
            tile[ty][tx] = rW[(size_t)(bj + ty) * 1024 + bk + tx];
        }
        __syncthreads();
        #pragma unroll
        for (int i = 0; i < 4; i++) {
            int ty = ty0 + i * 8;
            g_rWT[(size_t)(bk + ty) * 512 + bj + tx] = tile[tx][ty];
        }
    } else {                                              // feature mean
        int b = bid - 4352;
        for (int e = tid; e < EMB; e += 256) {
            const float* p = F + (size_t)b * NREG * EMB + e;
            float s = 0.f;
            #pragma unroll 4
            for (int n = 0; n < NREG; n++) s += p[(size_t)n * EMB];
            g_fmean[b * EMB + e] = s * (1.0f / NREG);
        }
    }
}

__global__ void k_init(const float* __restrict__ hW, const float* __restrict__ hb,
                       const float* __restrict__ cW, const float* __restrict__ cb) {
    int w = (blockIdx.x << 3) + (threadIdx.x >> 5);
    int lane = threadIdx.x & 31;
    int which = w >> 14;
    int bj = w & 16383;
    int b = bj >> 9, j = bj & 511;
    const float4* Wp = (const float4*)((which ? cW : hW) + (size_t)j * EMB);
    const float4* fp = (const float4*)(g_fmean + b * EMB);
    float s = 0.f;
    #pragma unroll
    for (int i = 0; i < 4; i++) {
        int id = lane + i * 32;
        float4 a = Wp[id], x = fp[id];
        s += a.x * x.x + a.y * x.y + a.z * x.z + a.w * x.w;
    }
    s = allsum(s);
    if (lane == 0) {
        if (which) g_c[b * HID + j] = s + cb[j];
        else       g_h[b * HID + j] = s + hb[j];
    }
}

// ---------------- generic 128x128 FFMA2 GEMM (fp32, used for hoists) ----------
// K = 512 always. transout=1 writes pre2T layout [(m&63)*2048+v]*32 + (m>>6).
__global__ void k_gemm(const float* __restrict__ A, int lda,
                       const float* __restrict__ Bm, int ldb,
                       const float* __restrict__ bias,
                       float* __restrict__ C, int ldc, int transout) {
    __shared__ float2 As2[16 * 129];
    __shared__ float  Bs [16 * 130];
    int tid = threadIdx.x;
    int tx = tid & 15, ty = tid >> 4;
    int vt = blockIdx.x * 128;
    int mt = blockIdx.y * 128;

    float2 acc[8][4];
    #pragma unroll
    for (int i = 0; i < 8; i++)
        #pragma unroll
        for (int q = 0; q < 4; q++) acc[i][q] = make_float2(0.f, 0.f);

    for (int kc = 0; kc < 32; kc++) {
        __syncthreads();
        #pragma unroll
        for (int i = 0; i < 2; i++) {
            int f4 = tid + i * 256;
            int m = f4 >> 2, kk = f4 & 3;
            float4 a = *(const float4*)(A + (size_t)(mt + m) * lda + kc * 16 + kk * 4);
            int kb = kk * 4;
            As2[(kb + 0) * 129 + m] = make_float2(a.x, a.x);
            As2[(kb + 1) * 129 + m] = make_float2(a.y, a.y);
            As2[(kb + 2) * 129 + m] = make_float2(a.z, a.z);
            As2[(kb + 3) * 129 + m] = make_float2(a.w, a.w);
            float4 bv = *(const float4*)(Bm + (size_t)(vt + m) * ldb + kc * 16 + kk * 4);
            Bs[(kb + 0) * 130 + m] = bv.x;
            Bs[(kb + 1) * 130 + m] = bv.y;
            Bs[(kb + 2) * 130 + m] = bv.z;
            Bs[(kb + 3) * 130 + m] = bv.w;
        }
        __syncthreads();
        #pragma unroll
        for (int k = 0; k < 16; k++) {
            float2 b2[4];
            #pragma unroll
            for (int q = 0; q < 4; q++)
                b2[q] = *(const float2*)&Bs[k * 130 + 2 * tx + 32 * q];
            #pragma unroll
            for (int i = 0; i < 8; i++) {
                float2 a2 = As2[k * 129 + ty * 8 + i];
                #pragma unroll
                for (int q = 0; q < 4; q++) ffma2(acc[i][q], a2, b2[q]);
            }
        }
    }
    #pragma unroll
    for (int q = 0; q < 4; q++) {
        int v = vt + 2 * tx + 32 * q;
        float2 bb = bias ? *(const float2*)(bias + v) : make_float2(0.f, 0.f);
        #pragma unroll
        for (int i = 0; i < 8; i++) {
            int m = mt + ty * 8 + i;
            float2 r = make_float2(acc[i][q].x + bb.x, acc[i][q].y + bb.y);
            if (!transout) {
                *(float2*)(C + (size_t)m * ldc + v) = r;
            } else {
                size_t base = ((size_t)((m & 63) * 2048 + v)) * 32 + (m >> 6);
                C[base]      = r.x;
                C[base + 32] = r.y;
            }
        }
    }
}

// ---------------- one-time: out_W -> tf32 bits ----------------
__global__ void k_cvtW(const float* __restrict__ oW) {
    int idx = blockIdx.x * 256 + threadIdx.x;            // 16000 blocks x 256 -> 4.096M uint4
    float4 v = ((const float4*)oW)[idx];
    uint4 u;
    u.x = f2tf32(v.x); u.y = f2tf32(v.y); u.z = f2tf32(v.z); u.w = f2tf32(v.w);
    ((uint4*)g_oWt)[idx] = u;
}

// ---------------- tf32 tensor-core output GEMM: out = H @ oW^T + ob ----------
// Pre-converted tf32 operands (g_Ht, g_oWt) + cp.async 2-stage pipeline.
// Tile 128x128, BK=32, 8 warps (4m x 2n), warp 32x64.
// dyn smem: 2 stages x (As 128*36 + Bs 128*36) uints = 73728 B
__global__ void __launch_bounds__(256, 1)
k_out_tc(const float* __restrict__ ob, float* __restrict__ out) {
    extern __shared__ unsigned sbuf[];
    int tid = threadIdx.x, lane = tid & 31, wid = tid >> 5;
    int wm = wid & 3, wn = wid >> 2;
    int vt = blockIdx.x * 128, mt = blockIdx.y * 128;
    unsigned sb = smem_u32(sbuf);

    float d[2][8][4];
    #pragma unroll
    for (int mi = 0; mi < 2; mi++)
        #pragma unroll
        for (int nj = 0; nj < 8; nj++)
            #pragma unroll
            for (int e = 0; e < 4; e++) d[mi][nj][e] = 0.f;

    int frow = tid >> 3;                 // 0..31
    int fcol = (tid & 7) * 4;            // 0..28
    // stage fill: 4 rows-per-thread x (A,B), 16B each
    #define FILL(ST, KC) do {                                                          \
        unsigned base = sb + (unsigned)(ST) * 36864u;                                  \
        _Pragma("unroll")                                                              \
        for (int i = 0; i < 4; i++) {                                                  \
            int row = frow + i * 32;                                                   \
            cpasync16(base + (unsigned)(row * 36 + fcol) * 4u,                         \
                      &g_Ht[(size_t)(mt + row) * 512 + (KC) * 32 + fcol]);             \
            cpasync16(base + 18432u + (unsigned)(row * 36 + fcol) * 4u,                \
                      &g_oWt[(size_t)(vt + row) * 512 + (KC) * 32 + fcol]);            \
        }                                                                              \
        asm volatile("cp.async.commit_group;" ::: "memory");                           \
    } while (0)

    FILL(0, 0);
    for (int kc = 0; kc < 16; kc++) {
        int st = kc & 1;
        if (kc + 1 < 16) FILL((kc + 1) & 1, kc + 1);
        if (kc < 15) asm volatile("cp.async.wait_group 1;" ::: "memory");
        else         asm volatile("cp.async.wait_group 0;" ::: "memory");
        __syncthreads();
        const unsigned* As  = sbuf + st * 9216;
        const unsigned* Bsm = As + 4608;
        int c = lane & 3, r = lane >> 2;
        #pragma unroll
        for (int k8 = 0; k8 < 4; k8++) {
            int k0 = k8 * 8;
            unsigned af[2][4];
            #pragma unroll
            for (int mi = 0; mi < 2; mi++) {
                int base = (wm * 32 + mi * 16 + r) * 36 + k0 + c;
                af[mi][0] = As[base];
                af[mi][1] = As[base + 8 * 36];
                af[mi][2] = As[base + 4];
                af[mi][3] = As[base + 8 * 36 + 4];
            }
            unsigned bf[8][2];
            #pragma unroll
            for (int nj = 0; nj < 8; nj++) {
                int base = (wn * 64 + nj * 8 + r) * 36 + k0 + c;
                bf[nj][0] = Bsm[base];
                bf[nj][1] = Bsm[base + 4];
            }
            #pragma unroll
            for (int mi = 0; mi < 2; mi++)
                #pragma unroll
                for (int nj = 0; nj < 8; nj++)
                    mma_tf32(d[mi][nj], af[mi], bf[nj]);
        }
        __syncthreads();                 // all warps done with stage st before refill
    }
    #undef FILL
    int c = lane & 3, r = lane >> 2;
    #pragma unroll
    for (int mi = 0; mi < 2; mi++) {
        #pragma unroll
        for (int nj = 0; nj < 8; nj++) {
            int m0 = mt + wm * 32 + mi * 16 + r;
            int v0 = vt + wn * 64 + nj * 8 + 2 * c;
            float2 bb = *(const float2*)(ob + v0);
            float2 r0 = make_float2(d[mi][nj][0] + bb.x, d[mi][nj][1] + bb.y);
            float2 r1 = make_float2(d[mi][nj][2] + bb.x, d[mi][nj][3] + bb.y);
            *(float2*)(out + (size_t)m0 * VOC + v0) = r0;
            *(float2*)(out + (size_t)(m0 + 8) * VOC + v0) = r1;
        }
    }
}

// ---------------- persistent fused recurrence ----------------
// grid = 148 CTAs x 256 thr. dyn smem 224768 B:
//   act4 [8448] float4 (hT rows 0..127, ctxT 128..255; [k4][b], pad 33)  135168
//   ws  [16384] float  (per-unit gate rows: [u][src][gate][512])          65536
//   abuf [1792] float  (per-warp attention weights)                        7168
//   redC2[4096] float  (phase C k-quarter partials: [w8][row16][lane32])  16384
//   redB  [128] float  (phase B n-split partials)                           512
__global__ void __launch_bounds__(256, 1)
k_rec(const float* __restrict__ F, const float* __restrict__ Whh,
      const float* __restrict__ bih, const float* __restrict__ bhh) {
    extern __shared__ float4 smem4[];
    float4* act4  = smem4;
    float*  ws    = (float*)(smem4 + 8448);
    float*  abuf  = ws + 16384;
    float*  redC2 = abuf + 1792;
    float*  redB  = redC2 + 4096;
    const int tid = threadIdx.x, lane = tid & 31, w = tid >> 5;
    const int cta = blockIdx.x;
    unsigned ep = 0;

    const int u  = w & 3;          // unit slot within CTA (phase B + weight staging)
    const int kh = w >> 2;         // half index (staging / phase B n-split)
    const int q  = cta + NCTA * u; // hidden unit owned by slot u
    const bool uvalid = (q < 512);

    // stage gate weights once: warp w stages src kh (0=M vs ctx, 1=Whh vs h) for unit u
    if (uvalid) {
        const float* src = kh ? Whh : g_M;
        #pragma unroll
        for (int g = 0; g < 4; g++) {
            const float* rp = src + (size_t)(q + g * 512) * 512;
            float* dst = ws + u * 4096 + kh * 2048 + g * 512;
            for (int j = lane; j < 512; j += 32) dst[j] = rp[j];
        }
    }
    float c_l = 0.f;
    float biasq[4] = {0.f, 0.f, 0.f, 0.f};
    if (uvalid && w < 4) {
        c_l = __ldcg(&g_c[lane * 512 + q]);
        #pragma unroll
        for (int g = 0; g < 4; g++) biasq[g] = bih[q + g * 512] + bhh[q + g * 512];
    }
    __syncthreads();

    const float4* F4 = (const float4*)F;
    const int gw = cta * 8 + w;

    for (int t = 0; t < SEQ; t++) {
        // ======== Phase A: stage hT; scores over all 8 warps ========
        {
            const float4* hg = (const float4*)g_h;
            for (int i = tid; i < 4096; i += 256) {
                float4 v = __ldcg(hg + i);
                act4[(i & 127) * 33 + (i >> 7)] = v;          // [k4][b]
            }
            __syncthreads();
            for (int dd = gw; dd < BB * NREG; dd += 1184) {
                int b = dd / NREG;
                const float4* fr = F4 + (size_t)dd * 128;
                float2 a = make_float2(0.f, 0.f);
                #pragma unroll
                for (int i = 0; i < 4; i++)
                    dotacc(a, fr[lane + 32 * i], act4[(lane + 32 * i) * 33 + b]);
                float s = allsum(a.x + a.y);
                if (lane == 0) g_sc[dd] = s;
            }
        }
        gbar(ep);
        // ======== Phase B: softmax (redundant per warp pair) + context, n-split
        {
            float csum = 0.f;
            int b = 0, ec = 0;
            if (uvalid) {
                int tb = q;
                b = tb >> 4; ec = tb & 15;
                float ev[7];
                float mx = -3.4e38f;
                #pragma unroll
                for (int j = 0; j < 7; j++) {
                    int n = lane + j * 32;
                    float s = (n < NREG) ? __ldcg(&g_sc[b * NREG + n]) : -3.4e38f;
                    ev[j] = s;
                    mx = fmaxf(mx, s);
                }
                mx = allmax(mx);
                float sum = 0.f;
                #pragma unroll
                for (int j = 0; j < 7; j++) {
                    int n = lane + j * 32;
                    float e = (n < NREG) ? expf(ev[j] - mx) : 0.f;
                    ev[j] = e;
                    sum += e;
                }
                sum = allsum(sum);
                float inv = 1.f / sum;
                float* ab = abuf + w * 224;
                #pragma unroll
                for (int j = 0; j < 7; j++) {
                    int n = lane + j * 32;
                    if (n < NREG) ab[n] = ev[j] * inv;
                }
                __syncwarp();
                const float* fp = F + (size_t)b * NREG * EMB + ec * 32 + lane;
                int n0 = kh ? 96 : 0, n1 = kh ? 196 : 96;
                float a8[8];
                #pragma unroll
                for (int j = 0; j < 8; j++) a8[j] = 0.f;
                int n = n0;
                for (; n + 8 <= n1; n += 8) {
                    #pragma unroll
                    for (int j = 0; j < 8; j++)
                        a8[j] = fmaf(ab[n + j], fp[(size_t)(n + j) * 512], a8[j]);
                }
                for (; n < n1; n++) a8[0] = fmaf(ab[n], fp[(size_t)n * 512], a8[0]);
                csum = ((a8[0] + a8[1]) + (a8[2] + a8[3]))
                     + ((a8[4] + a8[5]) + (a8[6] + a8[7]));
                if (kh) redB[u * 32 + lane] = csum;
            }
            __syncthreads();
            if (uvalid && kh == 0)
                g_ctx[b * 512 + ec * 32 + lane] = csum + redB[u * 32 + lane];
        }
        gbar(ep);
        // ======== Phase C: stage ctxT; k-quarter partials for ALL units; reduce;
        //          fused LSTM update ========
        {
            const float4* cg = (const float4*)g_ctx;
            for (int i = tid; i < 4096; i += 256) {
                float4 v = __ldcg(cg + i);
                act4[(128 + (i & 127)) * 33 + (i >> 7)] = v;
            }
            __syncthreads();
            // warp w covers 32 k4 rows: w<4 -> h rows (Whh, src1), w>=4 -> ctx rows (M, src0)
            {
                const int side = w >> 2;                  // 0:h rows  1:ctx rows
                const int qt = w & 3;
                const int baseRow = side * 128 + qt * 32;
                const int srcOff = side ? 0 : 2048;       // ctx->M(src0), h->Whh(src1)
                float2 pacc[4][4];
                #pragma unroll
                for (int uu = 0; uu < 4; uu++)
                    #pragma unroll
                    for (int g = 0; g < 4; g++) pacc[uu][g] = make_float2(0.f, 0.f);
                const float4* actp = act4 + (size_t)baseRow * 33 + lane;
                #pragma unroll 2
                for (int k4l = 0; k4l < 32; k4l++) {
                    float4 x = actp[k4l * 33];
                    #pragma unroll
                    for (int uu = 0; uu < 4; uu++) {
                        const float4* wp = (const float4*)(ws + uu * 4096 + srcOff)
                                         + qt * 32 + k4l;
                        #pragma unroll
                        for (int g = 0; g < 4; g++) {
                            float4 wg = wp[g * 128];      // gate stride 512 floats
                            ffma2(pacc[uu][g], make_float2(wg.x, wg.y),
                                               make_float2(x.x, x.y));
                            ffma2(pacc[uu][g], make_float2(wg.z, wg.w),
                                               make_float2(x.z, x.w));
                        }
                    }
                }
                float* rC = redC2 + w * 512;
                #pragma unroll
                for (int uu = 0; uu < 4; uu++)
                    #pragma unroll
                    for (int g = 0; g < 4; g++)
                        rC[(uu * 4 + g) * 32 + lane] = pacc[uu][g].x + pacc[uu][g].y;
            }
            __syncthreads();
            if (w < 4 && uvalid) {                        // u == w here
                float gate[4];
                size_t pb = ((size_t)(t * 2048 + q)) * 32 + lane;
                #pragma unroll
                for (int g = 0; g < 4; g++) {
                    float s = 0.f;
                    #pragma unroll
                    for (int j = 0; j < 8; j++)
                        s += redC2[j * 512 + (w * 4 + g) * 32 + lane];
                    gate[g] = s + g_pre2T[pb + (size_t)g * 16384] + biasq[g];
                }
                float si = 1.f / (1.f + expf(-gate[0]));
                float sf = 1.f / (1.f + expf(-gate[1]));
                float so = 1.f / (1.f + expf(-gate[3]));
                c_l = sf * c_l + si * tanhf(gate[2]);
                float h2v = so * tanhf(c_l);
                g_h[lane * 512 + q] = h2v;
                g_Ht[(size_t)((lane << 6) + t) * 512 + q] = f2tf32(h2v);
            }
        }
        gbar(ep);
    }
}

// ---------------- launch ----------------
extern "C" void kernel_launch(void* const* d_in, const int* in_sizes, int n_in,
                              void* d_out, int out_size) {
    const float* features = (const float*)d_in[0];
    const int*   captions = (const int*)  d_in[1];
    const float* embW     = (const float*)d_in[2];
    const float* ihW      = (const float*)d_in[3];
    const float* ihb      = (const float*)d_in[4];
    const float* icW      = (const float*)d_in[5];
    const float* icb      = (const float*)d_in[6];
    const float* rW       = (const float*)d_in[7];
    const float* rb       = (const float*)d_in[8];
    const float* Wih      = (const float*)d_in[9];
    const float* Whh      = (const float*)d_in[10];
    const float* bih      = (const float*)d_in[11];
    const float* bhh      = (const float*)d_in[12];
    const float* oW       = (const float*)d_in[13];
    const float* ob       = (const float*)d_in[14];
    float* out = (float*)d_out;

    static int inited = 0;
    static float *pEmb, *pXe, *pM, *pRWT, *pPre;
    if (!inited) {
        cudaFuncSetAttribute(k_rec, cudaFuncAttributeMaxDynamicSharedMemorySize, 224768);
        cudaFuncSetAttribute(k_out_tc, cudaFuncAttributeMaxDynamicSharedMemorySize, 73728);
        cudaGetSymbolAddress((void**)&pEmb, g_emb);
        cudaGetSymbolAddress((void**)&pXe,  g_xe);
        cudaGetSymbolAddress((void**)&pM,   g_M);
        cudaGetSymbolAddress((void**)&pRWT, g_rWT);
        cudaGetSymbolAddress((void**)&pPre, g_pre2T);
        inited = 1;
    }

    // launch 1: fused prep (embed + rW1 transpose + fmean) — also resets barrier
    k_prep<<<4384, 256>>>(captions, embW, rW, features);
    // launch 2
    k_init<<<4096, 256>>>(ihW, ihb, icW, icb);
    // launches 3-5: one-time algebraic hoists (fp32)
    k_gemm<<<dim3(4, 16), 256>>>(pEmb, 512, rW + 512, 1024, rb, pXe, 512, 0);   // xe
    k_gemm<<<dim3(4, 16), 256>>>(Wih, 512, pRWT, 512, nullptr, pM, 512, 0);     // M
    k_gemm<<<dim3(16, 16), 256>>>(pXe, 512, Wih, 512, nullptr, pPre, 0, 1);     // pre2T
    // launch 6: recurrence (ncu -s 5 -c 1 should land here)
    k_rec<<<NCTA, 256, 224768>>>(features, Whh, bih, bhh);
    // launch 7: out_W -> tf32 (independent of k_rec)
    k_cvtW<<<16000, 256>>>(oW);
    // launch 8: batched output projection (tf32 tensor cores, cp.async pipelined)
    k_out_tc<<<dim3(250, 16), 256, 73728>>>(ob, out);
}

// round 12
// speedup vs baseline: 3.1973x; 1.0563x over previous
#include <cuda_runtime.h>
#include <math.h>

#define BB   32
#define SEQ  64
#define EMB  512
#define HID  512
#define NREG 196
#define VOC  32000
#define SQRTE 22.62741699796952f
#define NCTA 148

// ---------------- device scratch (static; no runtime alloc) ----------------
__device__ float    g_emb[BB * SEQ * EMB];       // 4 MB  [m][e], m = b*64+t
__device__ float    g_fmean[BB * EMB];
__device__ float    g_h[BB * HID];
__device__ float    g_c[BB * HID];
__device__ float    g_sc[BB * NREG];
__device__ float    g_ctx[BB * EMB];
__device__ float    g_xe[BB * SEQ * EMB];        // 4 MB  emb-half of reshape (+rb)
__device__ unsigned g_Ht[BB * SEQ * HID];        // 4 MB  tf32 bits of H, row m=b*64+t
__device__ float    g_rWT[EMB * EMB];            // 1 MB  rW[:, :512] transposed
__device__ float    g_M[4 * HID * EMB];          // 4 MB  M = Wih @ rW1
__device__ float    g_pre2T[SEQ * 4 * HID * BB]; // 16 MB pre2T[t][r][b]
__device__ unsigned g_oWt[VOC * EMB];            // 65.5 MB tf32 bits of out_W
__device__ unsigned g_arrive;

// ---------------- helpers ----------------
__device__ __forceinline__ float allsum(float v) {
    #pragma unroll
    for (int o = 16; o > 0; o >>= 1) v += __shfl_xor_sync(0xffffffffu, v, o);
    return v;
}
__device__ __forceinline__ float allmax(float v) {
    #pragma unroll
    for (int o = 16; o > 0; o >>= 1) v = fmaxf(v, __shfl_xor_sync(0xffffffffu, v, o));
    return v;
}
// packed dual-FMA (FFMA2) — only reachable via PTX fma.rn.f32x2 on sm_10x
__device__ __forceinline__ void ffma2(float2& d, const float2& a, const float2& b) {
    asm("fma.rn.f32x2 %0, %1, %2, %0;"
        : "+l"(*reinterpret_cast<unsigned long long*>(&d))
        : "l"(*reinterpret_cast<const unsigned long long*>(&a)),
          "l"(*reinterpret_cast<const unsigned long long*>(&b)));
}
__device__ __forceinline__ void dotacc(float2& acc, const float4& w, const float4& v) {
    float2 a0 = make_float2(w.x, w.y), b0 = make_float2(v.x, v.y);
    ffma2(acc, a0, b0);
    float2 a1 = make_float2(w.z, w.w), b1 = make_float2(v.z, v.w);
    ffma2(acc, a1, b1);
}
__device__ __forceinline__ unsigned f2tf32(float x) {
    unsigned u;
    asm("cvt.rna.tf32.f32 %0, %1;" : "=r"(u) : "f"(x));
    return u;
}
__device__ __forceinline__ void mma_tf32(float* d, const unsigned* a, const unsigned* b) {
    asm("mma.sync.aligned.m16n8k8.row.col.f32.tf32.tf32.f32 "
        "{%0,%1,%2,%3}, {%4,%5,%6,%7}, {%8,%9}, {%0,%1,%2,%3};"
        : "+f"(d[0]), "+f"(d[1]), "+f"(d[2]), "+f"(d[3])
        : "r"(a[0]), "r"(a[1]), "r"(a[2]), "r"(a[3]), "r"(b[0]), "r"(b[1]));
}
__device__ __forceinline__ unsigned smem_u32(const void* p) {
    unsigned a;
    asm("{ .reg .u64 t; cvta.to.shared.u64 t, %1; cvt.u32.u64 %0, t; }"
        : "=r"(a) : "l"(p));
    return a;
}
__device__ __forceinline__ void cpasync16(unsigned s, const void* g) {
    asm volatile("cp.async.cg.shared.global [%0], [%1], 16;"
                 :: "r"(s), "l"((unsigned long long)__cvta_generic_to_global(g)));
}

// grid-wide software barrier (release/acquire; all cross-CTA mutable data is
// read via __ldcg (L2) so no L1 invalidation is needed). Requires grid == NCTA.
__device__ __forceinline__ void gbar(unsigned& ep) {
    ep += NCTA;
    __syncthreads();
    if (threadIdx.x == 0) {
        asm volatile("red.release.gpu.add.u32 [%0], %1;"
                     :: "l"(&g_arrive), "r"(1u) : "memory");
        unsigned v;
        do {
            asm volatile("ld.acquire.gpu.u32 %0, [%1];"
                         : "=r"(v) : "l"(&g_arrive) : "memory");
        } while (v < ep);
    }
    __syncthreads();
}

// ---------------- fused one-time prep: embed + rW1 transpose + fmean ----------
__global__ void k_prep(const int* __restrict__ caps, const float* __restrict__ embW,
                       const float* __restrict__ rW, const float* __restrict__ F) {
    __shared__ float tile[32][33];
    int bid = blockIdx.x, tid = threadIdx.x;
    if (bid == 0 && tid == 0) g_arrive = 0;              // barrier reset each launch
    if (bid < 4096) {                                     // embeddings
        int idx = bid * 256 + tid;
        int bt = idx >> 9, e = idx & 511;
        g_emb[idx] = embW[caps[bt] * 512 + e] * SQRTE;
    } else if (bid < 4352) {                              // rWT = rW[:, :512]^T
        int tI = bid - 4096;
        int bk = (tI & 15) * 32, bj = (tI >> 4) * 32;
        int tx = tid & 31, ty0 = tid >> 5;
        #pragma unroll
        for (int i = 0; i < 4; i++) {
            int ty = ty0 + i * 8;
            tile[ty][tx] = rW[(size_t)(bj + ty) * 1024 + bk + tx];
        }
        __syncthreads();
        #pragma unroll
        for (int i = 0; i < 4; i++) {
            int ty = ty0 + i * 8;
            g_rWT[(size_t)(bk + ty) * 512 + bj + tx] = tile[tx][ty];
        }
    } else {                                              // feature mean
        int b = bid - 4352;
        for (int e = tid; e < EMB; e += 256) {
            const float* p = F + (size_t)b * NREG * EMB + e;
            float s = 0.f;
            #pragma unroll 4
            for (int n = 0; n < NREG; n++) s += p[(size_t)n * EMB];
            g_fmean[b * EMB + e] = s * (1.0f / NREG);
        }
    }
}

__global__ void k_init(const float* __restrict__ hW, const float* __restrict__ hb,
                       const float* __restrict__ cW, const float* __restrict__ cb) {
    int w = (blockIdx.x << 3) + (threadIdx.x >> 5);
    int lane = threadIdx.x & 31;
    int which = w >> 14;
    int bj = w & 16383;
    int b = bj >> 9, j = bj & 511;
    const float4* Wp = (const float4*)((which ? cW : hW) + (size_t)j * EMB);
    const float4* fp = (const float4*)(g_fmean + b * EMB);
    float s = 0.f;
    #pragma unroll
    for (int i = 0; i < 4; i++) {
        int id = lane + i * 32;
        float4 a = Wp[id], x = fp[id];
        s += a.x * x.x + a.y * x.y + a.z * x.z + a.w * x.w;
    }
    s = allsum(s);
    if (lane == 0) {
        if (which) g_c[b * HID + j] = s + cb[j];
        else       g_h[b * HID + j] = s + hb[j];
    }
}

// ---------------- 128x64 FFMA2 GEMM (fp32 hoists; finer grid for occupancy) --
// K = 512 always. transout=1 writes pre2T layout [(m&63)*2048+v]*32 + (m>>6).
__global__ void k_gemm64(const float* __restrict__ A, int lda,
                         const float* __restrict__ Bm, int ldb,
                         const float* __restrict__ bias,
                         float* __restrict__ C, int ldc, int transout) {
    __shared__ float2 As2[16 * 129];
    __shared__ float  Bs [16 * 66];
    int tid = threadIdx.x;
    int tx = tid & 15, ty = tid >> 4;
    int vt = blockIdx.x * 64;
    int mt = blockIdx.y * 128;

    float2 acc[8][2];
    #pragma unroll
    for (int i = 0; i < 8; i++)
        #pragma unroll
        for (int q = 0; q < 2; q++) acc[i][q] = make_float2(0.f, 0.f);

    for (int kc = 0; kc < 32; kc++) {
        __syncthreads();
        #pragma unroll
        for (int i = 0; i < 2; i++) {                    // A: 512 float4
            int f4 = tid + i * 256;
            int m = f4 >> 2, kk = f4 & 3;
            float4 a = *(const float4*)(A + (size_t)(mt + m) * lda + kc * 16 + kk * 4);
            int kb = kk * 4;
            As2[(kb + 0) * 129 + m] = make_float2(a.x, a.x);
            As2[(kb + 1) * 129 + m] = make_float2(a.y, a.y);
            As2[(kb + 2) * 129 + m] = make_float2(a.z, a.z);
            As2[(kb + 3) * 129 + m] = make_float2(a.w, a.w);
        }
        {                                                // B: 256 float4
            int m = tid >> 2, kk = tid & 3;
            float4 bv = *(const float4*)(Bm + (size_t)(vt + m) * ldb + kc * 16 + kk * 4);
            int kb = kk * 4;
            Bs[(kb + 0) * 66 + m] = bv.x;
            Bs[(kb + 1) * 66 + m] = bv.y;
            Bs[(kb + 2) * 66 + m] = bv.z;
            Bs[(kb + 3) * 66 + m] = bv.w;
        }
        __syncthreads();
        #pragma unroll
        for (int k = 0; k < 16; k++) {
            float2 b2[2];
            #pragma unroll
            for (int q = 0; q < 2; q++)
                b2[q] = *(const float2*)&Bs[k * 66 + 2 * tx + 32 * q];
            #pragma unroll
            for (int i = 0; i < 8; i++) {
                float2 a2 = As2[k * 129 + ty * 8 + i];
                #pragma unroll
                for (int q = 0; q < 2; q++) ffma2(acc[i][q], a2, b2[q]);
            }
        }
    }
    #pragma unroll
    for (int q = 0; q < 2; q++) {
        int v = vt + 2 * tx + 32 * q;
        float2 bb = bias ? *(const float2*)(bias + v) : make_float2(0.f, 0.f);
        #pragma unroll
        for (int i = 0; i < 8; i++) {
            int m = mt + ty * 8 + i;
            float2 r = make_float2(acc[i][q].x + bb.x, acc[i][q].y + bb.y);
            if (!transout) {
                *(float2*)(C + (size_t)m * ldc + v) = r;
            } else {
                size_t base = ((size_t)((m & 63) * 2048 + v)) * 32 + (m >> 6);
                C[base]      = r.x;
                C[base + 32] = r.y;
            }
        }
    }
}

// ---------------- one-time: out_W -> tf32 bits ----------------
__global__ void k_cvtW(const float* __restrict__ oW) {
    int idx = blockIdx.x * 256 + threadIdx.x;            // 16000 blocks x 256 -> 4.096M uint4
    float4 v = ((const float4*)oW)[idx];
    uint4 u;
    u.x = f2tf32(v.x); u.y = f2tf32(v.y); u.z = f2tf32(v.z); u.w = f2tf32(v.w);
    ((uint4*)g_oWt)[idx] = u;
}

// ---------------- tf32 tensor-core output GEMM: out = H @ oW^T + ob ----------
// Pre-converted tf32 operands (g_Ht, g_oWt) + cp.async 2-stage pipeline.
// Grid (16 m, 250 v): a 148-CTA wave covers all 16 m-tiles x ~9 v-tiles, so
// each oW tile is DRAM-read once and L2-served to the 16 m-tiles.
__global__ void __launch_bounds__(256, 1)
k_out_tc(const float* __restrict__ ob, float* __restrict__ out) {
    extern __shared__ unsigned sbuf[];
    int tid = threadIdx.x, lane = tid & 31, wid = tid >> 5;
    int wm = wid & 3, wn = wid >> 2;
    int mt = blockIdx.x * 128, vt = blockIdx.y * 128;
    unsigned sb = smem_u32(sbuf);

    float d[2][8][4];
    #pragma unroll
    for (int mi = 0; mi < 2; mi++)
        #pragma unroll
        for (int nj = 0; nj < 8; nj++)
            #pragma unroll
            for (int e = 0; e < 4; e++) d[mi][nj][e] = 0.f;

    int frow = tid >> 3;                 // 0..31
    int fcol = (tid & 7) * 4;            // 0..28
    #define FILL(ST, KC) do {                                                          \
        unsigned base = sb + (unsigned)(ST) * 36864u;                                  \
        _Pragma("unroll")                                                              \
        for (int i = 0; i < 4; i++) {                                                  \
            int row = frow + i * 32;                                                   \
            cpasync16(base + (unsigned)(row * 36 + fcol) * 4u,                         \
                      &g_Ht[(size_t)(mt + row) * 512 + (KC) * 32 + fcol]);             \
            cpasync16(base + 18432u + (unsigned)(row * 36 + fcol) * 4u,                \
                      &g_oWt[(size_t)(vt + row) * 512 + (KC) * 32 + fcol]);            \
        }                                                                              \
        asm volatile("cp.async.commit_group;" ::: "memory");                           \
    } while (0)

    FILL(0, 0);
    for (int kc = 0; kc < 16; kc++) {
        int st = kc & 1;
        if (kc + 1 < 16) FILL((kc + 1) & 1, kc + 1);
        if (kc < 15) asm volatile("cp.async.wait_group 1;" ::: "memory");
        else         asm volatile("cp.async.wait_group 0;" ::: "memory");
        __syncthreads();
        const unsigned* As  = sbuf + st * 9216;
        const unsigned* Bsm = As + 4608;
        int c = lane & 3, r = lane >> 2;
        #pragma unroll
        for (int k8 = 0; k8 < 4; k8++) {
            int k0 = k8 * 8;
            unsigned af[2][4];
            #pragma unroll
            for (int mi = 0; mi < 2; mi++) {
                int base = (wm * 32 + mi * 16 + r) * 36 + k0 + c;
                af[mi][0] = As[base];
                af[mi][1] = As[base + 8 * 36];
                af[mi][2] = As[base + 4];
                af[mi][3] = As[base + 8 * 36 + 4];
            }
            unsigned bf[8][2];
            #pragma unroll
            for (int nj = 0; nj < 8; nj++) {
                int base = (wn * 64 + nj * 8 + r) * 36 + k0 + c;
                bf[nj][0] = Bsm[base];
                bf[nj][1] = Bsm[base + 4];
            }
            #pragma unroll
            for (int mi = 0; mi < 2; mi++)
                #pragma unroll
                for (int nj = 0; nj < 8; nj++)
                    mma_tf32(d[mi][nj], af[mi], bf[nj]);
        }
        __syncthreads();
    }
    #undef FILL
    int c = lane & 3, r = lane >> 2;
    #pragma unroll
    for (int mi = 0; mi < 2; mi++) {
        #pragma unroll
        for (int nj = 0; nj < 8; nj++) {
            int m0 = mt + wm * 32 + mi * 16 + r;
            int v0 = vt + wn * 64 + nj * 8 + 2 * c;
            float2 bb = *(const float2*)(ob + v0);
            float2 r0 = make_float2(d[mi][nj][0] + bb.x, d[mi][nj][1] + bb.y);
            float2 r1 = make_float2(d[mi][nj][2] + bb.x, d[mi][nj][3] + bb.y);
            *(float2*)(out + (size_t)m0 * VOC + v0) = r0;
            *(float2*)(out + (size_t)(m0 + 8) * VOC + v0) = r1;
        }
    }
}

// ---------------- persistent fused recurrence ----------------
// grid = 148 CTAs x 256 thr. dyn smem 224768 B (layout unchanged from R11).
__global__ void __launch_bounds__(256, 1)
k_rec(const float* __restrict__ F, const float* __restrict__ Whh,
      const float* __restrict__ bih, const float* __restrict__ bhh) {
    extern __shared__ float4 smem4[];
    float4* act4  = smem4;
    float*  ws    = (float*)(smem4 + 8448);
    float*  abuf  = ws + 16384;
    float*  redC2 = abuf + 1792;
    float*  redB  = redC2 + 4096;
    const int tid = threadIdx.x, lane = tid & 31, w = tid >> 5;
    const int cta = blockIdx.x;
    unsigned ep = 0;

    const int u  = w & 3;
    const int kh = w >> 2;
    const int q  = cta + NCTA * u;
    const bool uvalid = (q < 512);

    // stage gate weights once: warp w stages src kh (0=M vs ctx, 1=Whh vs h) for unit u
    if (uvalid) {
        const float* src = kh ? Whh : g_M;
        #pragma unroll
        for (int g = 0; g < 4; g++) {
            const float* rp = src + (size_t)(q + g * 512) * 512;
            float* dst = ws + u * 4096 + kh * 2048 + g * 512;
            for (int j = lane; j < 512; j += 32) dst[j] = rp[j];
        }
    }
    float c_l = 0.f;
    float biasq[4] = {0.f, 0.f, 0.f, 0.f};
    if (uvalid && w < 4) {
        c_l = __ldcg(&g_c[lane * 512 + q]);
        #pragma unroll
        for (int g = 0; g < 4; g++) biasq[g] = bih[q + g * 512] + bhh[q + g * 512];
    }
    __syncthreads();

    const float4* F4 = (const float4*)F;
    const int gw = cta * 8 + w;

    for (int t = 0; t < SEQ; t++) {
        // prefetch this step's pre2 gate terms (immutable) — consumed in phase C
        float pre[4];
        if (w < 4 && uvalid) {
            size_t pb = ((size_t)(t * 2048 + q)) * 32 + lane;
            #pragma unroll
            for (int g = 0; g < 4; g++) pre[g] = __ldg(&g_pre2T[pb + (size_t)g * 16384]);
        }
        // ======== Phase A: stage hT; scores over all 8 warps ========
        {
            const float4* hg = (const float4*)g_h;
            for (int i = tid; i < 4096; i += 256) {
                float4 v = __ldcg(hg + i);
                act4[(i & 127) * 33 + (i >> 7)] = v;          // [k4][b]
            }
            __syncthreads();
            for (int dd = gw; dd < BB * NREG; dd += 1184) {
                int b = dd / NREG;
                const float4* fr = F4 + (size_t)dd * 128;
                float2 a = make_float2(0.f, 0.f);
                #pragma unroll
                for (int i = 0; i < 4; i++)
                    dotacc(a, fr[lane + 32 * i], act4[(lane + 32 * i) * 33 + b]);
                float s = allsum(a.x + a.y);
                if (lane == 0) g_sc[dd] = s;
            }
        }
        gbar(ep);
        // ======== Phase B: softmax (redundant per warp pair) + context, n-split
        {
            float csum = 0.f;
            int b = 0, ec = 0;
            if (uvalid) {
                int tb = q;
                b = tb >> 4; ec = tb & 15;
                float ev[7];
                float mx = -3.4e38f;
                #pragma unroll
                for (int j = 0; j < 7; j++) {
                    int n = lane + j * 32;
                    float s = (n < NREG) ? __ldcg(&g_sc[b * NREG + n]) : -3.4e38f;
                    ev[j] = s;
                    mx = fmaxf(mx, s);
                }
                mx = allmax(mx);
                float sum = 0.f;
                #pragma unroll
                for (int j = 0; j < 7; j++) {
                    int n = lane + j * 32;
                    float e = (n < NREG) ? expf(ev[j] - mx) : 0.f;
                    ev[j] = e;
                    sum += e;
                }
                sum = allsum(sum);
                float inv = 1.f / sum;
                float* ab = abuf + w * 224;
                #pragma unroll
                for (int j = 0; j < 7; j++) {
                    int n = lane + j * 32;
                    if (n < NREG) ab[n] = ev[j] * inv;
                }
                __syncwarp();
                const float* fp = F + (size_t)b * NREG * EMB + ec * 32 + lane;
                int n0 = kh ? 96 : 0, n1 = kh ? 196 : 96;
                float a8[8];
                #pragma unroll
                for (int j = 0; j < 8; j++) a8[j] = 0.f;
                int n = n0;
                for (; n + 8 <= n1; n += 8) {
                    #pragma unroll
                    for (int j = 0; j < 8; j++)
                        a8[j] = fmaf(ab[n + j], fp[(size_t)(n + j) * 512], a8[j]);
                }
                for (; n < n1; n++) a8[0] = fmaf(ab[n], fp[(size_t)n * 512], a8[0]);
                csum = ((a8[0] + a8[1]) + (a8[2] + a8[3]))
                     + ((a8[4] + a8[5]) + (a8[6] + a8[7]));
                if (kh) redB[u * 32 + lane] = csum;
            }
            __syncthreads();
            if (uvalid && kh == 0)
                g_ctx[b * 512 + ec * 32 + lane] = csum + redB[u * 32 + lane];
        }
        gbar(ep);
        // ======== Phase C: stage ctxT; k-quarter partials for ALL units; reduce;
        //          fused LSTM update ========
        {
            const float4* cg = (const float4*)g_ctx;
            for (int i = tid; i < 4096; i += 256) {
                float4 v = __ldcg(cg + i);
                act4[(128 + (i & 127)) * 33 + (i >> 7)] = v;
            }
            __syncthreads();
            {
                const int side = w >> 2;                  // 0:h rows  1:ctx rows
                const int qt = w & 3;
                const int baseRow = side * 128 + qt * 32;
                const int srcOff = side ? 0 : 2048;       // ctx->M(src0), h->Whh(src1)
                float2 pacc[4][4];
                #pragma unroll
                for (int uu = 0; uu < 4; uu++)
                    #pragma unroll
                    for (int g = 0; g < 4; g++) pacc[uu][g] = make_float2(0.f, 0.f);
                const float4* actp = act4 + (size_t)baseRow * 33 + lane;
                #pragma unroll 2
                for (int k4l = 0; k4l < 32; k4l++) {
                    float4 x = actp[k4l * 33];
                    #pragma unroll
                    for (int uu = 0; uu < 4; uu++) {
                        const float4* wp = (const float4*)(ws + uu * 4096 + srcOff)
                                         + qt * 32 + k4l;
                        #pragma unroll
                        for (int g = 0; g < 4; g++) {
                            float4 wg = wp[g * 128];
                            ffma2(pacc[uu][g], make_float2(wg.x, wg.y),
                                               make_float2(x.x, x.y));
                            ffma2(pacc[uu][g], make_float2(wg.z, wg.w),
                                               make_float2(x.z, x.w));
                        }
                    }
                }
                float* rC = redC2 + w * 512;
                #pragma unroll
                for (int uu = 0; uu < 4; uu++)
                    #pragma unroll
                    for (int g = 0; g < 4; g++)
                        rC[(uu * 4 + g) * 32 + lane] = pacc[uu][g].x + pacc[uu][g].y;
            }
            __syncthreads();
            if (w < 4 && uvalid) {                        // u == w here
                float gate[4];
                #pragma unroll
                for (int g = 0; g < 4; g++) {
                    float s = 0.f;
                    #pragma unroll
                    for (int j = 0; j < 8; j++)
                        s += redC2[j * 512 + (w * 4 + g) * 32 + lane];
                    gate[g] = s + pre[g] + biasq[g];
                }
                float si = 1.f / (1.f + expf(-gate[0]));
                float sf = 1.f / (1.f + expf(-gate[1]));
                float so = 1.f / (1.f + expf(-gate[3]));
                c_l = sf * c_l + si * tanhf(gate[2]);
                float h2v = so * tanhf(c_l);
                g_h[lane * 512 + q] = h2v;
                g_Ht[(size_t)((lane << 6) + t) * 512 + q] = f2tf32(h2v);
            }
        }
        gbar(ep);
    }
}

// ---------------- launch ----------------
extern "C" void kernel_launch(void* const* d_in, const int* in_sizes, int n_in,
                              void* d_out, int out_size) {
    const float* features = (const float*)d_in[0];
    const int*   captions = (const int*)  d_in[1];
    const float* embW     = (const float*)d_in[2];
    const float* ihW      = (const float*)d_in[3];
    const float* ihb      = (const float*)d_in[4];
    const float* icW      = (const float*)d_in[5];
    const float* icb      = (const float*)d_in[6];
    const float* rW       = (const float*)d_in[7];
    const float* rb       = (const float*)d_in[8];
    const float* Wih      = (const float*)d_in[9];
    const float* Whh      = (const float*)d_in[10];
    const float* bih      = (const float*)d_in[11];
    const float* bhh      = (const float*)d_in[12];
    const float* oW       = (const float*)d_in[13];
    const float* ob       = (const float*)d_in[14];
    float* out = (float*)d_out;

    static int inited = 0;
    static float *pEmb, *pXe, *pM, *pRWT, *pPre;
    if (!inited) {
        cudaFuncSetAttribute(k_rec, cudaFuncAttributeMaxDynamicSharedMemorySize, 224768);
        cudaFuncSetAttribute(k_out_tc, cudaFuncAttributeMaxDynamicSharedMemorySize, 73728);
        cudaGetSymbolAddress((void**)&pEmb, g_emb);
        cudaGetSymbolAddress((void**)&pXe,  g_xe);
        cudaGetSymbolAddress((void**)&pM,   g_M);
        cudaGetSymbolAddress((void**)&pRWT, g_rWT);
        cudaGetSymbolAddress((void**)&pPre, g_pre2T);
        inited = 1;
    }

    // fused prep (embed + rW1 transpose + fmean) — also resets barrier
    k_prep<<<4384, 256>>>(captions, embW, rW, features);
    k_init<<<4096, 256>>>(ihW, ihb, icW, icb);
    // one-time algebraic hoists (fp32, 128x64 tiles for full-chip occupancy)
    k_gemm64<<<dim3(8, 16),  256>>>(pEmb, 512, rW + 512, 1024, rb, pXe, 512, 0); // xe
    k_gemm64<<<dim3(8, 16),  256>>>(Wih, 512, pRWT, 512, nullptr, pM, 512, 0);   // M
    k_gemm64<<<dim3(32, 16), 256>>>(pXe, 512, Wih, 512, nullptr, pPre, 0, 1);    // pre2T
    // recurrence
    k_rec<<<NCTA, 256, 224768>>>(features, Whh, bih, bhh);
    // out_W -> tf32 (independent of k_rec)
    k_cvtW<<<16000, 256>>>(oW);
    // batched output projection (tf32 tensor cores, cp.async pipelined, m-major waves)
    k_out_tc<<<dim3(16, 250), 256, 73728>>>(ob, out);
}

// round 13
// speedup vs baseline: 3.2705x; 1.0229x over previous
#include <cuda_runtime.h>
#include <math.h>

#define BB   32
#define SEQ  64
#define EMB  512
#define HID  512
#define NREG 196
#define VOC  32000
#define SQRTE 22.62741699796952f
#define NCTA 148

// ---------------- device scratch (static; no runtime alloc) ----------------
__device__ float    g_emb[BB * SEQ * EMB];       // 4 MB  [m][e], m = b*64+t
__device__ float    g_h[BB * HID];
__device__ float    g_c[BB * HID];
__device__ float    g_sc[BB * NREG];
__device__ float    g_ctx[BB * EMB];
__device__ float    g_xe[BB * SEQ * EMB];        // 4 MB  emb-half of reshape (+rb)
__device__ unsigned g_Ht[BB * SEQ * HID];        // 4 MB  tf32 bits of H, row m=b*64+t
__device__ float    g_rWT[EMB * EMB];            // 1 MB  rW[:, :512] transposed
__device__ float    g_M[4 * HID * EMB];          // 4 MB  M = Wih @ rW1
__device__ float    g_pre2T[SEQ * 4 * HID * BB]; // 16 MB pre2T[t][r][b]
__device__ unsigned g_oWt[VOC * EMB];            // 65.5 MB tf32 bits of out_W
__device__ unsigned g_arrive;

// ---------------- helpers ----------------
__device__ __forceinline__ float allsum(float v) {
    #pragma unroll
    for (int o = 16; o > 0; o >>= 1) v += __shfl_xor_sync(0xffffffffu, v, o);
    return v;
}
__device__ __forceinline__ float allmax(float v) {
    #pragma unroll
    for (int o = 16; o > 0; o >>= 1) v = fmaxf(v, __shfl_xor_sync(0xffffffffu, v, o));
    return v;
}
// packed dual-FMA (FFMA2) — only reachable via PTX fma.rn.f32x2 on sm_10x
__device__ __forceinline__ void ffma2(float2& d, const float2& a, const float2& b) {
    asm("fma.rn.f32x2 %0, %1, %2, %0;"
        : "+l"(*reinterpret_cast<unsigned long long*>(&d))
        : "l"(*reinterpret_cast<const unsigned long long*>(&a)),
          "l"(*reinterpret_cast<const unsigned long long*>(&b)));
}
__device__ __forceinline__ void dotacc(float2& acc, const float4& w, const float4& v) {
    float2 a0 = make_float2(w.x, w.y), b0 = make_float2(v.x, v.y);
    ffma2(acc, a0, b0);
    float2 a1 = make_float2(w.z, w.w), b1 = make_float2(v.z, v.w);
    ffma2(acc, a1, b1);
}
__device__ __forceinline__ unsigned f2tf32(float x) {
    unsigned u;
    asm("cvt.rna.tf32.f32 %0, %1;" : "=r"(u) : "f"(x));
    return u;
}
__device__ __forceinline__ void mma_tf32(float* d, const unsigned* a, const unsigned* b) {
    asm("mma.sync.aligned.m16n8k8.row.col.f32.tf32.tf32.f32 "
        "{%0,%1,%2,%3}, {%4,%5,%6,%7}, {%8,%9}, {%0,%1,%2,%3};"
        : "+f"(d[0]), "+f"(d[1]), "+f"(d[2]), "+f"(d[3])
        : "r"(a[0]), "r"(a[1]), "r"(a[2]), "r"(a[3]), "r"(b[0]), "r"(b[1]));
}
__device__ __forceinline__ unsigned smem_u32(const void* p) {
    unsigned a;
    asm("{ .reg .u64 t; cvta.to.shared.u64 t, %1; cvt.u32.u64 %0, t; }"
        : "=r"(a) : "l"(p));
    return a;
}
__device__ __forceinline__ void cpasync16(unsigned s, const void* g) {
    asm volatile("cp.async.cg.shared.global [%0], [%1], 16;"
                 :: "r"(s), "l"((unsigned long long)__cvta_generic_to_global(g)));
}

// grid-wide software barrier (release/acquire; all cross-CTA mutable data is
// read via __ldcg (L2) so no L1 invalidation is needed). Requires grid == NCTA.
__device__ __forceinline__ void gbar(unsigned& ep) {
    ep += NCTA;
    __syncthreads();
    if (threadIdx.x == 0) {
        asm volatile("red.release.gpu.add.u32 [%0], %1;"
                     :: "l"(&g_arrive), "r"(1u) : "memory");
        unsigned v;
        do {
            asm volatile("ld.acquire.gpu.u32 %0, [%1];"
                         : "=r"(v) : "l"(&g_arrive) : "memory");
        } while (v < ep);
    }
    __syncthreads();
}

// ---------------- fused one-time prep (launch 0) ----------------------------
// blocks [0,4096):      embeddings
// blocks [4096,4352):   rWT = rW[:, :512]^T
// blocks [4352,4416):   h0/c0 init (each CTA computes fmean[b] redundantly)
// blocks [4416,20416):  out_W -> tf32 bits
__global__ void k_prep(const int* __restrict__ caps, const float* __restrict__ embW,
                       const float* __restrict__ rW, const float* __restrict__ F,
                       const float* __restrict__ hW, const float* __restrict__ hb,
                       const float* __restrict__ cW, const float* __restrict__ cb,
                       const float* __restrict__ oW) {
    __shared__ float tile[32][33];
    __shared__ float sfm[512];
    int bid = blockIdx.x, tid = threadIdx.x;
    if (bid == 0 && tid == 0) g_arrive = 0;               // barrier reset each launch
    if (bid < 4096) {                                     // embeddings
        int idx = bid * 256 + tid;
        int bt = idx >> 9, e = idx & 511;
        g_emb[idx] = embW[caps[bt] * 512 + e] * SQRTE;
    } else if (bid < 4352) {                              // rWT
        int tI = bid - 4096;
        int bk = (tI & 15) * 32, bj = (tI >> 4) * 32;
        int tx = tid & 31, ty0 = tid >> 5;
        #pragma unroll
        for (int i = 0; i < 4; i++) {
            int ty = ty0 + i * 8;
            tile[ty][tx] = rW[(size_t)(bj + ty) * 1024 + bk + tx];
        }
        __syncthreads();
        #pragma unroll
        for (int i = 0; i < 4; i++) {
            int ty = ty0 + i * 8;
            g_rWT[(size_t)(bk + ty) * 512 + bj + tx] = tile[tx][ty];
        }
    } else if (bid < 4416) {                              // h0/c0 init
        int bid2 = bid - 4352;
        int which = bid2 >> 5, b = bid2 & 31;
        // fmean[b] (redundant per CTA)
        #pragma unroll
        for (int rep = 0; rep < 2; rep++) {
            int e = tid + rep * 256;
            const float* p = F + (size_t)b * NREG * EMB + e;
            float s0 = 0.f, s1 = 0.f;
            #pragma unroll 2
            for (int n = 0; n < NREG; n += 2) {
                s0 += p[(size_t)n * EMB];
                if (n + 1 < NREG) s1 += p[(size_t)(n + 1) * EMB];
            }
            sfm[e] = (s0 + s1) * (1.0f / NREG);
        }
        __syncthreads();
        int lane = tid & 31, w = tid >> 5;
        const float* Wm = which ? cW : hW;
        const float* bv = which ? cb : hb;
        const float4* fp = (const float4*)sfm;
        for (int jj = 0; jj < 64; jj++) {
            int j = w * 64 + jj;
            const float4* Wp = (const float4*)(Wm + (size_t)j * EMB);
            float s = 0.f;
            #pragma unroll
            for (int i = 0; i < 4; i++) {
                int id = lane + i * 32;
                float4 a = Wp[id], x = fp[id];
                s += a.x * x.x + a.y * x.y + a.z * x.z + a.w * x.w;
            }
            s = allsum(s);
            if (lane == 0) {
                if (which) g_c[b * HID + j] = s + bv[j];
                else       g_h[b * HID + j] = s + bv[j];
            }
        }
    } else {                                              // out_W -> tf32
        int idx = (bid - 4416) * 256 + tid;               // 4.096M uint4
        float4 v = ((const float4*)oW)[idx];
        uint4 u;
        u.x = f2tf32(v.x); u.y = f2tf32(v.y); u.z = f2tf32(v.z); u.w = f2tf32(v.w);
        ((uint4*)g_oWt)[idx] = u;
    }
}

// ---------------- fused xe + M hoist GEMM (launch 1), 128x64 FFMA2 tiles -----
// z=0: xe = emb @ rW2^T + rb   z=1: M = Wih @ rW1 (via rWT rows)
__global__ void k_gemmXM(const float* __restrict__ rW, const float* __restrict__ rb,
                         const float* __restrict__ Wih) {
    __shared__ float2 As2[16 * 129];
    __shared__ float  Bs [16 * 66];
    int z = blockIdx.z;
    const float* A    = z ? Wih  : g_emb;
    const float* Bm   = z ? g_rWT : rW + 512;
    const float* bias = z ? (const float*)0 : rb;
    float*       C    = z ? g_M  : g_xe;
    const int ldb     = z ? 512 : 1024;
    int tid = threadIdx.x;
    int tx = tid & 15, ty = tid >> 4;
    int vt = blockIdx.x * 64;
    int mt = blockIdx.y * 128;

    float2 acc[8][2];
    #pragma unroll
    for (int i = 0; i < 8; i++)
        #pragma unroll
        for (int q = 0; q < 2; q++) acc[i][q] = make_float2(0.f, 0.f);

    for (int kc = 0; kc < 32; kc++) {
        __syncthreads();
        #pragma unroll
        for (int i = 0; i < 2; i++) {
            int f4 = tid + i * 256;
            int m = f4 >> 2, kk = f4 & 3;
            float4 a = *(const float4*)(A + (size_t)(mt + m) * 512 + kc * 16 + kk * 4);
            int kb = kk * 4;
            As2[(kb + 0) * 129 + m] = make_float2(a.x, a.x);
            As2[(kb + 1) * 129 + m] = make_float2(a.y, a.y);
            As2[(kb + 2) * 129 + m] = make_float2(a.z, a.z);
            As2[(kb + 3) * 129 + m] = make_float2(a.w, a.w);
        }
        {
            int m = tid >> 2, kk = tid & 3;
            float4 bvv = *(const float4*)(Bm + (size_t)(vt + m) * ldb + kc * 16 + kk * 4);
            int kb = kk * 4;
            Bs[(kb + 0) * 66 + m] = bvv.x;
            Bs[(kb + 1) * 66 + m] = bvv.y;
            Bs[(kb + 2) * 66 + m] = bvv.z;
            Bs[(kb + 3) * 66 + m] = bvv.w;
        }
        __syncthreads();
        #pragma unroll
        for (int k = 0; k < 16; k++) {
            float2 b2[2];
            #pragma unroll
            for (int q = 0; q < 2; q++)
                b2[q] = *(const float2*)&Bs[k * 66 + 2 * tx + 32 * q];
            #pragma unroll
            for (int i = 0; i < 8; i++) {
                float2 a2 = As2[k * 129 + ty * 8 + i];
                #pragma unroll
                for (int q = 0; q < 2; q++) ffma2(acc[i][q], a2, b2[q]);
            }
        }
    }
    #pragma unroll
    for (int q = 0; q < 2; q++) {
        int v = vt + 2 * tx + 32 * q;
        float2 bb = bias ? *(const float2*)(bias + v) : make_float2(0.f, 0.f);
        #pragma unroll
        for (int i = 0; i < 8; i++) {
            int m = mt + ty * 8 + i;
            float2 r = make_float2(acc[i][q].x + bb.x, acc[i][q].y + bb.y);
            *(float2*)(C + (size_t)m * 512 + v) = r;
        }
    }
}

// ---------------- pre2T hoist GEMM (launch 2), 128x64, transposed output -----
__global__ void k_gemm64(const float* __restrict__ A, int lda,
                         const float* __restrict__ Bm, int ldb,
                         const float* __restrict__ bias,
                         float* __restrict__ C, int ldc, int transout) {
    __shared__ float2 As2[16 * 129];
    __shared__ float  Bs [16 * 66];
    int tid = threadIdx.x;
    int tx = tid & 15, ty = tid >> 4;
    int vt = blockIdx.x * 64;
    int mt = blockIdx.y * 128;

    float2 acc[8][2];
    #pragma unroll
    for (int i = 0; i < 8; i++)
        #pragma unroll
        for (int q = 0; q < 2; q++) acc[i][q] = make_float2(0.f, 0.f);

    for (int kc = 0; kc < 32; kc++) {
        __syncthreads();
        #pragma unroll
        for (int i = 0; i < 2; i++) {
            int f4 = tid + i * 256;
            int m = f4 >> 2, kk = f4 & 3;
            float4 a = *(const float4*)(A + (size_t)(mt + m) * lda + kc * 16 + kk * 4);
            int kb = kk * 4;
            As2[(kb + 0) * 129 + m] = make_float2(a.x, a.x);
            As2[(kb + 1) * 129 + m] = make_float2(a.y, a.y);
            As2[(kb + 2) * 129 + m] = make_float2(a.z, a.z);
            As2[(kb + 3) * 129 + m] = make_float2(a.w, a.w);
        }
        {
            int m = tid >> 2, kk = tid & 3;
            float4 bv = *(const float4*)(Bm + (size_t)(vt + m) * ldb + kc * 16 + kk * 4);
            int kb = kk * 4;
            Bs[(kb + 0) * 66 + m] = bv.x;
            Bs[(kb + 1) * 66 + m] = bv.y;
            Bs[(kb + 2) * 66 + m] = bv.z;
            Bs[(kb + 3) * 66 + m] = bv.w;
        }
        __syncthreads();
        #pragma unroll
        for (int k = 0; k < 16; k++) {
            float2 b2[2];
            #pragma unroll
            for (int q = 0; q < 2; q++)
                b2[q] = *(const float2*)&Bs[k * 66 + 2 * tx + 32 * q];
            #pragma unroll
            for (int i = 0; i < 8; i++) {
                float2 a2 = As2[k * 129 + ty * 8 + i];
                #pragma unroll
                for (int q = 0; q < 2; q++) ffma2(acc[i][q], a2, b2[q]);
            }
        }
    }
    #pragma unroll
    for (int q = 0; q < 2; q++) {
        int v = vt + 2 * tx + 32 * q;
        float2 bb = bias ? *(const float2*)(bias + v) : make_float2(0.f, 0.f);
        #pragma unroll
        for (int i = 0; i < 8; i++) {
            int m = mt + ty * 8 + i;
            float2 r = make_float2(acc[i][q].x + bb.x, acc[i][q].y + bb.y);
            if (!transout) {
                *(float2*)(C + (size_t)m * ldc + v) = r;
            } else {
                size_t base = ((size_t)((m & 63) * 2048 + v)) * 32 + (m >> 6);
                C[base]      = r.x;
                C[base + 32] = r.y;
            }
        }
    }
}

// ---------------- tf32 tensor-core output GEMM (launch 4) --------------------
// 256x128 tiles (halves operand traffic vs 128x128), cp.async 2-stage pipeline,
// streaming (__stcs) output stores to avoid evicting oWt from L2.
// 8 warps (4m x 2n), warp tile 64x64. dyn smem: 2 x (256+128)x36 uints = 110592 B
__global__ void __launch_bounds__(256, 1)
k_out_tc(const float* __restrict__ ob, float* __restrict__ out) {
    extern __shared__ unsigned sbuf[];
    int tid = threadIdx.x, lane = tid & 31, wid = tid >> 5;
    int wm = wid & 3, wn = wid >> 2;
    int mt = blockIdx.x * 256, vt = blockIdx.y * 128;
    unsigned sb = smem_u32(sbuf);

    float d[4][8][4];
    #pragma unroll
    for (int mi = 0; mi < 4; mi++)
        #pragma unroll
        for (int nj = 0; nj < 8; nj++)
            #pragma unroll
            for (int e = 0; e < 4; e++) d[mi][nj][e] = 0.f;

    int frow = tid >> 3;                 // 0..31
    int fcol = (tid & 7) * 4;            // 0..28
    #define FILL(ST, KC) do {                                                          \
        unsigned base = sb + (unsigned)(ST) * 55296u;                                  \
        _Pragma("unroll")                                                              \
        for (int i = 0; i < 8; i++) {                                                  \
            int row = frow + i * 32;                                                   \
            cpasync16(base + (unsigned)(row * 36 + fcol) * 4u,                         \
                      &g_Ht[(size_t)(mt + row) * 512 + (KC) * 32 + fcol]);             \
        }                                                                              \
        _Pragma("unroll")                                                              \
        for (int i = 0; i < 4; i++) {                                                  \
            int row = frow + i * 32;                                                   \
            cpasync16(base + 36864u + (unsigned)(row * 36 + fcol) * 4u,                \
                      &g_oWt[(size_t)(vt + row) * 512 + (KC) * 32 + fcol]);            \
        }                                                                              \
        asm volatile("cp.async.commit_group;" ::: "memory");                           \
    } while (0)

    FILL(0, 0);
    for (int kc = 0; kc < 16; kc++) {
        int st = kc & 1;
        if (kc + 1 < 16) FILL((kc + 1) & 1, kc + 1);
        if (kc < 15) asm volatile("cp.async.wait_group 1;" ::: "memory");
        else         asm volatile("cp.async.wait_group 0;" ::: "memory");
        __syncthreads();
        const unsigned* As  = sbuf + st * 13824;
        const unsigned* Bsm = As + 9216;
        int c = lane & 3, r = lane >> 2;
        #pragma unroll
        for (int k8 = 0; k8 < 4; k8++) {
            int k0 = k8 * 8;
            unsigned af[4][4];
            #pragma unroll
            for (int mi = 0; mi < 4; mi++) {
                int base = (wm * 64 + mi * 16 + r) * 36 + k0 + c;
                af[mi][0] = As[base];
                af[mi][1] = As[base + 8 * 36];
                af[mi][2] = As[base + 4];
                af[mi][3] = As[base + 8 * 36 + 4];
            }
            unsigned bf[8][2];
            #pragma unroll
            for (int nj = 0; nj < 8; nj++) {
                int base = (wn * 64 + nj * 8 + r) * 36 + k0 + c;
                bf[nj][0] = Bsm[base];
                bf[nj][1] = Bsm[base + 4];
            }
            #pragma unroll
            for (int mi = 0; mi < 4; mi++)
                #pragma unroll
                for (int nj = 0; nj < 8; nj++)
                    mma_tf32(d[mi][nj], af[mi], bf[nj]);
        }
        __syncthreads();
    }
    #undef FILL
    int c = lane & 3, r = lane >> 2;
    #pragma unroll
    for (int mi = 0; mi < 4; mi++) {
        #pragma unroll
        for (int nj = 0; nj < 8; nj++) {
            int m0 = mt + wm * 64 + mi * 16 + r;
            int v0 = vt + wn * 64 + nj * 8 + 2 * c;
            float2 bb = *(const float2*)(ob + v0);
            float2 r0 = make_float2(d[mi][nj][0] + bb.x, d[mi][nj][1] + bb.y);
            float2 r1 = make_float2(d[mi][nj][2] + bb.x, d[mi][nj][3] + bb.y);
            __stcs((float2*)(out + (size_t)m0 * VOC + v0), r0);
            __stcs((float2*)(out + (size_t)(m0 + 8) * VOC + v0), r1);
        }
    }
}

// ---------------- persistent fused recurrence (launch 3 — ncu slot) ----------
// grid = 148 CTAs x 256 thr. dyn smem 224768 B (unchanged control variable).
__global__ void __launch_bounds__(256, 1)
k_rec(const float* __restrict__ F, const float* __restrict__ Whh,
      const float* __restrict__ bih, const float* __restrict__ bhh) {
    extern __shared__ float4 smem4[];
    float4* act4  = smem4;
    float*  ws    = (float*)(smem4 + 8448);
    float*  abuf  = ws + 16384;
    float*  redC2 = abuf + 1792;
    float*  redB  = redC2 + 4096;
    const int tid = threadIdx.x, lane = tid & 31, w = tid >> 5;
    const int cta = blockIdx.x;
    unsigned ep = 0;

    const int u  = w & 3;
    const int kh = w >> 2;
    const int q  = cta + NCTA * u;
    const bool uvalid = (q < 512);

    if (uvalid) {
        const float* src = kh ? Whh : g_M;
        #pragma unroll
        for (int g = 0; g < 4; g++) {
            const float* rp = src + (size_t)(q + g * 512) * 512;
            float* dst = ws + u * 4096 + kh * 2048 + g * 512;
            for (int j = lane; j < 512; j += 32) dst[j] = rp[j];
        }
    }
    float c_l = 0.f;
    float biasq[4] = {0.f, 0.f, 0.f, 0.f};
    if (uvalid && w < 4) {
        c_l = __ldcg(&g_c[lane * 512 + q]);
        #pragma unroll
        for (int g = 0; g < 4; g++) biasq[g] = bih[q + g * 512] + bhh[q + g * 512];
    }
    __syncthreads();

    const float4* F4 = (const float4*)F;
    const int gw = cta * 8 + w;

    for (int t = 0; t < SEQ; t++) {
        float pre[4];
        if (w < 4 && uvalid) {
            size_t pb = ((size_t)(t * 2048 + q)) * 32 + lane;
            #pragma unroll
            for (int g = 0; g < 4; g++) pre[g] = __ldg(&g_pre2T[pb + (size_t)g * 16384]);
        }
        // ======== Phase A: stage hT; scores over all 8 warps ========
        {
            const float4* hg = (const float4*)g_h;
            for (int i = tid; i < 4096; i += 256) {
                float4 v = __ldcg(hg + i);
                act4[(i & 127) * 33 + (i >> 7)] = v;
            }
            __syncthreads();
            for (int dd = gw; dd < BB * NREG; dd += 1184) {
                int b = dd / NREG;
                const float4* fr = F4 + (size_t)dd * 128;
                float2 a = make_float2(0.f, 0.f);
                #pragma unroll
                for (int i = 0; i < 4; i++)
                    dotacc(a, fr[lane + 32 * i], act4[(lane + 32 * i) * 33 + b]);
                float s = allsum(a.x + a.y);
                if (lane == 0) g_sc[dd] = s;
            }
        }
        gbar(ep);
        // ======== Phase B: softmax (redundant per warp pair) + context, n-split
        {
            float csum = 0.f;
            int b = 0, ec = 0;
            if (uvalid) {
                int tb = q;
                b = tb >> 4; ec = tb & 15;
                float ev[7];
                float mx = -3.4e38f;
                #pragma unroll
                for (int j = 0; j < 7; j++) {
                    int n = lane + j * 32;
                    float s = (n < NREG) ? __ldcg(&g_sc[b * NREG + n]) : -3.4e38f;
                    ev[j] = s;
                    mx = fmaxf(mx, s);
                }
                mx = allmax(mx);
                float sum = 0.f;
                #pragma unroll
                for (int j = 0; j < 7; j++) {
                    int n = lane + j * 32;
                    float e = (n < NREG) ? expf(ev[j] - mx) : 0.f;
                    ev[j] = e;
                    sum += e;
                }
                sum = allsum(sum);
                float inv = 1.f / sum;
                float* ab = abuf + w * 224;
                #pragma unroll
                for (int j = 0; j < 7; j++) {
                    int n = lane + j * 32;
                    if (n < NREG) ab[n] = ev[j] * inv;
                }
                __syncwarp();
                const float* fp = F + (size_t)b * NREG * EMB + ec * 32 + lane;
                int n0 = kh ? 96 : 0, n1 = kh ? 196 : 96;
                float a8[8];
                #pragma unroll
                for (int j = 0; j < 8; j++) a8[j] = 0.f;
                int n = n0;
                for (; n + 8 <= n1; n += 8) {
                    #pragma unroll
                    for (int j = 0; j < 8; j++)
                        a8[j] = fmaf(ab[n + j], fp[(size_t)(n + j) * 512], a8[j]);
                }
                for (; n < n1; n++) a8[0] = fmaf(ab[n], fp[(size_t)n * 512], a8[0]);
                csum = ((a8[0] + a8[1]) + (a8[2] + a8[3]))
                     + ((a8[4] + a8[5]) + (a8[6] + a8[7]));
                if (kh) redB[u * 32 + lane] = csum;
            }
            __syncthreads();
            if (uvalid && kh == 0)
                g_ctx[b * 512 + ec * 32 + lane] = csum + redB[u * 32 + lane];
        }
        gbar(ep);
        // ======== Phase C: stage ctxT; k-quarter partials for ALL units; reduce;
        //          fused LSTM update ========
        {
            const float4* cg = (const float4*)g_ctx;
            for (int i = tid; i < 4096; i += 256) {
                float4 v = __ldcg(cg + i);
                act4[(128 + (i & 127)) * 33 + (i >> 7)] = v;
            }
            __syncthreads();
            {
                const int side = w >> 2;
                const int qt = w & 3;
                const int baseRow = side * 128 + qt * 32;
                const int srcOff = side ? 0 : 2048;
                float2 pacc[4][4];
                #pragma unroll
                for (int uu = 0; uu < 4; uu++)
                    #pragma unroll
                    for (int g = 0; g < 4; g++) pacc[uu][g] = make_float2(0.f, 0.f);
                const float4* actp = act4 + (size_t)baseRow * 33 + lane;
                #pragma unroll 2
                for (int k4l = 0; k4l < 32; k4l++) {
                    float4 x = actp[k4l * 33];
                    #pragma unroll
                    for (int uu = 0; uu < 4; uu++) {
                        const float4* wp = (const float4*)(ws + uu * 4096 + srcOff)
                                         + qt * 32 + k4l;
                        #pragma unroll
                        for (int g = 0; g < 4; g++) {
                            float4 wg = wp[g * 128];
                            ffma2(pacc[uu][g], make_float2(wg.x, wg.y),
                                               make_float2(x.x, x.y));
                            ffma2(pacc[uu][g], make_float2(wg.z, wg.w),
                                               make_float2(x.z, x.w));
                        }
                    }
                }
                float* rC = redC2 + w * 512;
                #pragma unroll
                for (int uu = 0; uu < 4; uu++)
                    #pragma unroll
                    for (int g = 0; g < 4; g++)
                        rC[(uu * 4 + g) * 32 + lane] = pacc[uu][g].x + pacc[uu][g].y;
            }
            __syncthreads();
            if (w < 4 && uvalid) {
                float gate[4];
                #pragma unroll
                for (int g = 0; g < 4; g++) {
                    float s = 0.f;
                    #pragma unroll
                    for (int j = 0; j < 8; j++)
                        s += redC2[j * 512 + (w * 4 + g) * 32 + lane];
                    gate[g] = s + pre[g] + biasq[g];
                }
                float si = 1.f / (1.f + expf(-gate[0]));
                float sf = 1.f / (1.f + expf(-gate[1]));
                float so = 1.f / (1.f + expf(-gate[3]));
                c_l = sf * c_l + si * tanhf(gate[2]);
                float h2v = so * tanhf(c_l);
                g_h[lane * 512 + q] = h2v;
                g_Ht[(size_t)((lane << 6) + t) * 512 + q] = f2tf32(h2v);
            }
        }
        gbar(ep);
    }
}

// ---------------- launch ----------------
extern "C" void kernel_launch(void* const* d_in, const int* in_sizes, int n_in,
                              void* d_out, int out_size) {
    const float* features = (const float*)d_in[0];
    const int*   captions = (const int*)  d_in[1];
    const float* embW     = (const float*)d_in[2];
    const float* ihW      = (const float*)d_in[3];
    const float* ihb      = (const float*)d_in[4];
    const float* icW      = (const float*)d_in[5];
    const float* icb      = (const float*)d_in[6];
    const float* rW       = (const float*)d_in[7];
    const float* rb       = (const float*)d_in[8];
    const float* Wih      = (const float*)d_in[9];
    const float* Whh      = (const float*)d_in[10];
    const float* bih      = (const float*)d_in[11];
    const float* bhh      = (const float*)d_in[12];
    const float* oW       = (const float*)d_in[13];
    const float* ob       = (const float*)d_in[14];
    float* out = (float*)d_out;

    static int inited = 0;
    static float *pXe, *pPre;
    if (!inited) {
        cudaFuncSetAttribute(k_rec, cudaFuncAttributeMaxDynamicSharedMemorySize, 224768);
        cudaFuncSetAttribute(k_out_tc, cudaFuncAttributeMaxDynamicSharedMemorySize, 110592);
        cudaGetSymbolAddress((void**)&pXe,  g_xe);
        cudaGetSymbolAddress((void**)&pPre, g_pre2T);
        inited = 1;
    }

    // launch 0: fused prep (embed + rW1 transpose + init(own fmean) + cvtW)
    k_prep<<<20416, 256>>>(captions, embW, rW, features, ihW, ihb, icW, icb, oW);
    // launch 1: fused xe + M hoists
    k_gemmXM<<<dim3(8, 16, 2), 256>>>(rW, rb, Wih);
    // launch 2: pre2T = xe @ Wih^T (transposed output layout)
    k_gemm64<<<dim3(32, 16), 256>>>(pXe, 512, Wih, 512, nullptr, pPre, 0, 1);
    // launch 3: recurrence  <-- ncu profiles this slot
    k_rec<<<NCTA, 256, 224768>>>(features, Whh, bih, bhh);
    // launch 4: batched output projection (tf32 MMA, 256x128 tiles, streaming stores)
    k_out_tc<<<dim3(8, 250), 256, 110592>>>(ob, out);
}

// round 15
// speedup vs baseline: 3.4440x; 1.0530x over previous
#include <cuda_runtime.h>
#include <math.h>

#define BB   32
#define SEQ  64
#define EMB  512
#define HID  512
#define NREG 196
#define VOC  32000
#define SQRTE 22.62741699796952f
#define NCTA 148
#define RTHREADS 384
#define RWARPS 12

// ---------------- device scratch (static; no runtime alloc) ----------------
__device__ float    g_emb[BB * SEQ * EMB];       // 4 MB  [m][e], m = b*64+t
__device__ float    g_h[BB * HID];
__device__ float    g_c[BB * HID];
__device__ float    g_sc[BB * NREG];
__device__ float    g_ctx[BB * EMB];
__device__ float    g_xe[BB * SEQ * EMB];        // 4 MB  emb-half of reshape (+rb)
__device__ unsigned g_Ht[BB * SEQ * HID];        // 4 MB  tf32 bits of H, row m=b*64+t
__device__ float    g_rWT[EMB * EMB];            // 1 MB  rW[:, :512] transposed
__device__ float    g_M[4 * HID * EMB];          // 4 MB  M = Wih @ rW1
__device__ float    g_pre2T[SEQ * 4 * HID * BB]; // 16 MB pre2T[t][r][b]
__device__ unsigned g_oWt[VOC * EMB];            // 65.5 MB tf32 bits of out_W
__device__ unsigned g_arrive;

// ---------------- helpers ----------------
__device__ __forceinline__ float allsum(float v) {
    #pragma unroll
    for (int o = 16; o > 0; o >>= 1) v += __shfl_xor_sync(0xffffffffu, v, o);
    return v;
}
__device__ __forceinline__ float allmax(float v) {
    #pragma unroll
    for (int o = 16; o > 0; o >>= 1) v = fmaxf(v, __shfl_xor_sync(0xffffffffu, v, o));
    return v;
}
// packed dual-FMA (FFMA2) — only reachable via PTX fma.rn.f32x2 on sm_10x
__device__ __forceinline__ void ffma2(float2& d, const float2& a, const float2& b) {
    asm("fma.rn.f32x2 %0, %1, %2, %0;"
        : "+l"(*reinterpret_cast<unsigned long long*>(&d))
        : "l"(*reinterpret_cast<const unsigned long long*>(&a)),
          "l"(*reinterpret_cast<const unsigned long long*>(&b)));
}
__device__ __forceinline__ void dotacc(float2& acc, const float4& w, const float4& v) {
    float2 a0 = make_float2(w.x, w.y), b0 = make_float2(v.x, v.y);
    ffma2(acc, a0, b0);
    float2 a1 = make_float2(w.z, w.w), b1 = make_float2(v.z, v.w);
    ffma2(acc, a1, b1);
}
__device__ __forceinline__ unsigned f2tf32(float x) {
    unsigned u;
    asm("cvt.rna.tf32.f32 %0, %1;" : "=r"(u) : "f"(x));
    return u;
}
__device__ __forceinline__ void mma_tf32(float* d, const unsigned* a, const unsigned* b) {
    asm("mma.sync.aligned.m16n8k8.row.col.f32.tf32.tf32.f32 "
        "{%0,%1,%2,%3}, {%4,%5,%6,%7}, {%8,%9}, {%0,%1,%2,%3};"
        : "+f"(d[0]), "+f"(d[1]), "+f"(d[2]), "+f"(d[3])
        : "r"(a[0]), "r"(a[1]), "r"(a[2]), "r"(a[3]), "r"(b[0]), "r"(b[1]));
}
__device__ __forceinline__ unsigned smem_u32(const void* p) {
    unsigned a;
    asm("{ .reg .u64 t; cvta.to.shared.u64 t, %1; cvt.u32.u64 %0, t; }"
        : "=r"(a) : "l"(p));
    return a;
}
__device__ __forceinline__ void cpasync16(unsigned s, const void* g) {
    asm volatile("cp.async.cg.shared.global [%0], [%1], 16;"
                 :: "r"(s), "l"((unsigned long long)__cvta_generic_to_global(g)));
}

// grid-wide software barrier (release/acquire). Requires grid == NCTA.
__device__ __forceinline__ void gbar(unsigned& ep) {
    ep += NCTA;
    __syncthreads();
    if (threadIdx.x == 0) {
        asm volatile("red.release.gpu.add.u32 [%0], %1;"
                     :: "l"(&g_arrive), "r"(1u) : "memory");
        unsigned v;
        do {
            asm volatile("ld.acquire.gpu.u32 %0, [%1];"
                         : "=r"(v) : "l"(&g_arrive) : "memory");
        } while (v < ep);
    }
    __syncthreads();
}

// ---------------- fused one-time prep (launch 0) ----------------------------
__global__ void k_prep(const int* __restrict__ caps, const float* __restrict__ embW,
                       const float* __restrict__ rW, const float* __restrict__ F,
                       const float* __restrict__ hW, const float* __restrict__ hb,
                       const float* __restrict__ cW, const float* __restrict__ cb,
                       const float* __restrict__ oW) {
    __shared__ float tile[32][33];
    __shared__ float sfm[512];
    int bid = blockIdx.x, tid = threadIdx.x;
    if (bid == 0 && tid == 0) g_arrive = 0;               // barrier reset each launch
    if (bid < 4096) {                                     // embeddings
        int idx = bid * 256 + tid;
        int bt = idx >> 9, e = idx & 511;
        g_emb[idx] = embW[caps[bt] * 512 + e] * SQRTE;
    } else if (bid < 4352) {                              // rWT
        int tI = bid - 4096;
        int bk = (tI & 15) * 32, bj = (tI >> 4) * 32;
        int tx = tid & 31, ty0 = tid >> 5;
        #pragma unroll
        for (int i = 0; i < 4; i++) {
            int ty = ty0 + i * 8;
            tile[ty][tx] = rW[(size_t)(bj + ty) * 1024 + bk + tx];
        }
        __syncthreads();
        #pragma unroll
        for (int i = 0; i < 4; i++) {
            int ty = ty0 + i * 8;
            g_rWT[(size_t)(bk + ty) * 512 + bj + tx] = tile[tx][ty];
        }
    } else if (bid < 4416) {                              // h0/c0 init
        int bid2 = bid - 4352;
        int which = bid2 >> 5, b = bid2 & 31;
        #pragma unroll
        for (int rep = 0; rep < 2; rep++) {
            int e = tid + rep * 256;
            const float* p = F + (size_t)b * NREG * EMB + e;
            float s0 = 0.f, s1 = 0.f;
            #pragma unroll 2
            for (int n = 0; n < NREG; n += 2) {
                s0 += p[(size_t)n * EMB];
                if (n + 1 < NREG) s1 += p[(size_t)(n + 1) * EMB];
            }
            sfm[e] = (s0 + s1) * (1.0f / NREG);
        }
        __syncthreads();
        int lane = tid & 31, w = tid >> 5;
        const float* Wm = which ? cW : hW;
        const float* bv = which ? cb : hb;
        const float4* fp = (const float4*)sfm;
        for (int jj = 0; jj < 64; jj++) {
            int j = w * 64 + jj;
            const float4* Wp = (const float4*)(Wm + (size_t)j * EMB);
            float s = 0.f;
            #pragma unroll
            for (int i = 0; i < 4; i++) {
                int id = lane + i * 32;
                float4 a = Wp[id], x = fp[id];
                s += a.x * x.x + a.y * x.y + a.z * x.z + a.w * x.w;
            }
            s = allsum(s);
            if (lane == 0) {
                if (which) g_c[b * HID + j] = s + bv[j];
                else       g_h[b * HID + j] = s + bv[j];
            }
        }
    } else {                                              // out_W -> tf32
        int idx = (bid - 4416) * 256 + tid;
        float4 v = ((const float4*)oW)[idx];
        uint4 u;
        u.x = f2tf32(v.x); u.y = f2tf32(v.y); u.z = f2tf32(v.z); u.w = f2tf32(v.w);
        ((uint4*)g_oWt)[idx] = u;
    }
}

// ---------------- fused xe + M hoist GEMM (launch 1), 128x64 FFMA2 tiles -----
__global__ void k_gemmXM(const float* __restrict__ rW, const float* __restrict__ rb,
                         const float* __restrict__ Wih) {
    __shared__ float2 As2[16 * 129];
    __shared__ float  Bs [16 * 66];
    int z = blockIdx.z;
    const float* A    = z ? Wih  : g_emb;
    const float* Bm   = z ? g_rWT : rW + 512;
    const float* bias = z ? (const float*)0 : rb;
    float*       C    = z ? g_M  : g_xe;
    const int ldb     = z ? 512 : 1024;
    int tid = threadIdx.x;
    int tx = tid & 15, ty = tid >> 4;
    int vt = blockIdx.x * 64;
    int mt = blockIdx.y * 128;

    float2 acc[8][2];
    #pragma unroll
    for (int i = 0; i < 8; i++)
        #pragma unroll
        for (int q = 0; q < 2; q++) acc[i][q] = make_float2(0.f, 0.f);

    for (int kc = 0; kc < 32; kc++) {
        __syncthreads();
        #pragma unroll
        for (int i = 0; i < 2; i++) {
            int f4 = tid + i * 256;
            int m = f4 >> 2, kk = f4 & 3;
            float4 a = *(const float4*)(A + (size_t)(mt + m) * 512 + kc * 16 + kk * 4);
            int kb = kk * 4;
            As2[(kb + 0) * 129 + m] = make_float2(a.x, a.x);
            As2[(kb + 1) * 129 + m] = make_float2(a.y, a.y);
            As2[(kb + 2) * 129 + m] = make_float2(a.z, a.z);
            As2[(kb + 3) * 129 + m] = make_float2(a.w, a.w);
        }
        {
            int m = tid >> 2, kk = tid & 3;
            float4 bvv = *(const float4*)(Bm + (size_t)(vt + m) * ldb + kc * 16 + kk * 4);
            int kb = kk * 4;
            Bs[(kb + 0) * 66 + m] = bvv.x;
            Bs[(kb + 1) * 66 + m] = bvv.y;
            Bs[(kb + 2) * 66 + m] = bvv.z;
            Bs[(kb + 3) * 66 + m] = bvv.w;
        }
        __syncthreads();
        #pragma unroll
        for (int k = 0; k < 16; k++) {
            float2 b2[2];
            #pragma unroll
            for (int q = 0; q < 2; q++)
                b2[q] = *(const float2*)&Bs[k * 66 + 2 * tx + 32 * q];
            #pragma unroll
            for (int i = 0; i < 8; i++) {
                float2 a2 = As2[k * 129 + ty * 8 + i];
                #pragma unroll
                for (int q = 0; q < 2; q++) ffma2(acc[i][q], a2, b2[q]);
            }
        }
    }
    #pragma unroll
    for (int q = 0; q < 2; q++) {
        int v = vt + 2 * tx + 32 * q;
        float2 bb = bias ? *(const float2*)(bias + v) : make_float2(0.f, 0.f);
        #pragma unroll
        for (int i = 0; i < 8; i++) {
            int m = mt + ty * 8 + i;
            float2 r = make_float2(acc[i][q].x + bb.x, acc[i][q].y + bb.y);
            *(float2*)(C + (size_t)m * 512 + v) = r;
        }
    }
}

// ---------------- pre2T hoist GEMM (launch 2), 128x64, transposed output -----
__global__ void k_gemm64(const float* __restrict__ A, int lda,
                         const float* __restrict__ Bm, int ldb,
                         const float* __restrict__ bias,
                         float* __restrict__ C, int ldc, int transout) {
    __shared__ float2 As2[16 * 129];
    __shared__ float  Bs [16 * 66];
    int tid = threadIdx.x;
    int tx = tid & 15, ty = tid >> 4;
    int vt = blockIdx.x * 64;
    int mt = blockIdx.y * 128;

    float2 acc[8][2];
    #pragma unroll
    for (int i = 0; i < 8; i++)
        #pragma unroll
        for (int q = 0; q < 2; q++) acc[i][q] = make_float2(0.f, 0.f);

    for (int kc = 0; kc < 32; kc++) {
        __syncthreads();
        #pragma unroll
        for (int i = 0; i < 2; i++) {
            int f4 = tid + i * 256;
            int m = f4 >> 2, kk = f4 & 3;
            float4 a = *(const float4*)(A + (size_t)(mt + m) * lda + kc * 16 + kk * 4);
            int kb = kk * 4;
            As2[(kb + 0) * 129 + m] = make_float2(a.x, a.x);
            As2[(kb + 1) * 129 + m] = make_float2(a.y, a.y);
            As2[(kb + 2) * 129 + m] = make_float2(a.z, a.z);
            As2[(kb + 3) * 129 + m] = make_float2(a.w, a.w);
        }
        {
            int m = tid >> 2, kk = tid & 3;
            float4 bv = *(const float4*)(Bm + (size_t)(vt + m) * ldb + kc * 16 + kk * 4);
            int kb = kk * 4;
            Bs[(kb + 0) * 66 + m] = bv.x;
            Bs[(kb + 1) * 66 + m] = bv.y;
            Bs[(kb + 2) * 66 + m] = bv.z;
            Bs[(kb + 3) * 66 + m] = bv.w;
        }
        __syncthreads();
        #pragma unroll
        for (int k = 0; k < 16; k++) {
            float2 b2[2];
            #pragma unroll
            for (int q = 0; q < 2; q++)
                b2[q] = *(const float2*)&Bs[k * 66 + 2 * tx + 32 * q];
            #pragma unroll
            for (int i = 0; i < 8; i++) {
                float2 a2 = As2[k * 129 + ty * 8 + i];
                #pragma unroll
                for (int q = 0; q < 2; q++) ffma2(acc[i][q], a2, b2[q]);
            }
        }
    }
    #pragma unroll
    for (int q = 0; q < 2; q++) {
        int v = vt + 2 * tx + 32 * q;
        float2 bb = bias ? *(const float2*)(bias + v) : make_float2(0.f, 0.f);
        #pragma unroll
        for (int i = 0; i < 8; i++) {
            int m = mt + ty * 8 + i;
            float2 r = make_float2(acc[i][q].x + bb.x, acc[i][q].y + bb.y);
            if (!transout) {
                *(float2*)(C + (size_t)m * ldc + v) = r;
            } else {
                size_t base = ((size_t)((m & 63) * 2048 + v)) * 32 + (m >> 6);
                C[base]      = r.x;
                C[base + 32] = r.y;
            }
        }
    }
}

// ---------------- tf32 tensor-core output GEMM (launch 4, unchanged) ---------
__global__ void __launch_bounds__(256, 1)
k_out_tc(const float* __restrict__ ob, float* __restrict__ out) {
    extern __shared__ unsigned sbuf[];
    int tid = threadIdx.x, lane = tid & 31, wid = tid >> 5;
    int wm = wid & 3, wn = wid >> 2;
    int mt = blockIdx.x * 256, vt = blockIdx.y * 128;
    unsigned sb = smem_u32(sbuf);

    float d[4][8][4];
    #pragma unroll
    for (int mi = 0; mi < 4; mi++)
        #pragma unroll
        for (int nj = 0; nj < 8; nj++)
            #pragma unroll
            for (int e = 0; e < 4; e++) d[mi][nj][e] = 0.f;

    int frow = tid >> 3;
    int fcol = (tid & 7) * 4;
    #define FILL(ST, KC) do {                                                          \
        unsigned base = sb + (unsigned)(ST) * 55296u;                                  \
        _Pragma("unroll")                                                              \
        for (int i = 0; i < 8; i++) {                                                  \
            int row = frow + i * 32;                                                   \
            cpasync16(base + (unsigned)(row * 36 + fcol) * 4u,                         \
                      &g_Ht[(size_t)(mt + row) * 512 + (KC) * 32 + fcol]);             \
        }                                                                              \
        _Pragma("unroll")                                                              \
        for (int i = 0; i < 4; i++) {                                                  \
            int row = frow + i * 32;                                                   \
            cpasync16(base + 36864u + (unsigned)(row * 36 + fcol) * 4u,                \
                      &g_oWt[(size_t)(vt + row) * 512 + (KC) * 32 + fcol]);            \
        }                                                                              \
        asm volatile("cp.async.commit_group;" ::: "memory");                           \
    } while (0)

    FILL(0, 0);
    for (int kc = 0; kc < 16; kc++) {
        int st = kc & 1;
        if (kc + 1 < 16) FILL((kc + 1) & 1, kc + 1);
        if (kc < 15) asm volatile("cp.async.wait_group 1;" ::: "memory");
        else         asm volatile("cp.async.wait_group 0;" ::: "memory");
        __syncthreads();
        const unsigned* As  = sbuf + st * 13824;
        const unsigned* Bsm = As + 9216;
        int c = lane & 3, r = lane >> 2;
        #pragma unroll
        for (int k8 = 0; k8 < 4; k8++) {
            int k0 = k8 * 8;
            unsigned af[4][4];
            #pragma unroll
            for (int mi = 0; mi < 4; mi++) {
                int base = (wm * 64 + mi * 16 + r) * 36 + k0 + c;
                af[mi][0] = As[base];
                af[mi][1] = As[base + 8 * 36];
                af[mi][2] = As[base + 4];
                af[mi][3] = As[base + 8 * 36 + 4];
            }
            unsigned bf[8][2];
            #pragma unroll
            for (int nj = 0; nj < 8; nj++) {
                int base = (wn * 64 + nj * 8 + r) * 36 + k0 + c;
                bf[nj][0] = Bsm[base];
                bf[nj][1] = Bsm[base + 4];
            }
            #pragma unroll
            for (int mi = 0; mi < 4; mi++)
                #pragma unroll
                for (int nj = 0; nj < 8; nj++)
                    mma_tf32(d[mi][nj], af[mi], bf[nj]);
        }
        __syncthreads();
    }
    #undef FILL
    int c = lane & 3, r = lane >> 2;
    #pragma unroll
    for (int mi = 0; mi < 4; mi++) {
        #pragma unroll
        for (int nj = 0; nj < 8; nj++) {
            int m0 = mt + wm * 64 + mi * 16 + r;
            int v0 = vt + wn * 64 + nj * 8 + 2 * c;
            float2 bb = *(const float2*)(ob + v0);
            float2 r0 = make_float2(d[mi][nj][0] + bb.x, d[mi][nj][1] + bb.y);
            float2 r1 = make_float2(d[mi][nj][2] + bb.x, d[mi][nj][3] + bb.y);
            __stcs((float2*)(out + (size_t)m0 * VOC + v0), r0);
            __stcs((float2*)(out + (size_t)(m0 + 8) * VOC + v0), r1);
        }
    }
}

// ---------------- persistent fused recurrence (launch 3, 384 threads) --------
// grid = 148 CTAs x 384 thr. dyn smem 228864 B:
//   act4 [8448] float4 (hT rows 0..127, ctxT 128..255; [k4][b], pad 33)  135168
//   ws  [16384] float  (per-unit gate rows: [u][src][gate][512])          65536
//   abuf [2688] float  (per-warp attention weights, 12 x 224)             10752
//   redC2[4096] float  (phase C 8-way k partials)                         16384
//   redB  [256] float  (phase B 3-way n partials: [u][third-1][lane])      1024
__global__ void __launch_bounds__(RTHREADS, 1)
k_rec(const float* __restrict__ F, const float* __restrict__ Whh,
      const float* __restrict__ bih, const float* __restrict__ bhh) {
    extern __shared__ float4 smem4[];
    float4* act4  = smem4;
    float*  ws    = (float*)(smem4 + 8448);
    float*  abuf  = ws + 16384;
    float*  redC2 = abuf + 2688;
    float*  redB  = redC2 + 4096;
    const int tid = threadIdx.x, lane = tid & 31, w = tid >> 5;   // w: 0..11
    const int cta = blockIdx.x;
    unsigned ep = 0;

    const int u   = w & 3;          // unit slot (phase B, weight staging)
    const int nt3 = w >> 2;         // phase B n-third: 0,1,2
    const int q   = cta + NCTA * u;
    const bool uvalid = (q < 512);

    // stage gate weights once: warps 0..7 (u = w&3, src half kh = w>>2)
    if (w < 8 && uvalid) {
        const int kh = w >> 2;
        const float* src = kh ? Whh : g_M;
        #pragma unroll
        for (int g = 0; g < 4; g++) {
            const float* rp = src + (size_t)(q + g * 512) * 512;
            float* dst = ws + u * 4096 + kh * 2048 + g * 512;
            for (int j = lane; j < 512; j += 32) dst[j] = rp[j];
        }
    }
    float c_l = 0.f;
    float biasq[4] = {0.f, 0.f, 0.f, 0.f};
    if (uvalid && w < 4) {
        c_l = __ldcg(&g_c[lane * 512 + q]);
        #pragma unroll
        for (int g = 0; g < 4; g++) biasq[g] = bih[q + g * 512] + bhh[q + g * 512];
    }
    __syncthreads();

    const float4* F4 = (const float4*)F;
    const int gw = cta * RWARPS + w;                  // 0..1775

    for (int t = 0; t < SEQ; t++) {
        float pre[4];
        if (w < 4 && uvalid) {
            size_t pb = ((size_t)(t * 2048 + q)) * 32 + lane;
            #pragma unroll
            for (int g = 0; g < 4; g++) pre[g] = __ldg(&g_pre2T[pb + (size_t)g * 16384]);
        }
        // ======== Phase A: stage hT; dual-dot scores over all 12 warps ========
        {
            const float4* hg = (const float4*)g_h;
            for (int i = tid; i < 4096; i += RTHREADS) {
                float4 v = __ldcg(hg + i);
                act4[(i & 127) * 33 + (i >> 7)] = v;
            }
            __syncthreads();
            // dots at gw, gw+1776, gw+3552, gw+5280 — process in interleaved pairs
            #pragma unroll
            for (int p = 0; p < 2; p++) {
                int d0 = gw + p * 3552;
                int d1 = d0 + 1776;
                bool v1 = (d1 < BB * NREG);           // d0 always < 6272 for p<2? p=1: d0<5328 ✓
                int b0 = d0 / NREG;
                int b1 = v1 ? (d1 / NREG) : b0;
                const float4* fr0 = F4 + (size_t)d0 * 128;
                const float4* fr1 = F4 + (size_t)(v1 ? d1 : d0) * 128;
                float2 a0 = make_float2(0.f, 0.f), a1 = make_float2(0.f, 0.f);
                #pragma unroll
                for (int i = 0; i < 4; i++) {
                    int id = lane + 32 * i;
                    dotacc(a0, fr0[id], act4[id * 33 + b0]);
                    dotacc(a1, fr1[id], act4[id * 33 + b1]);
                }
                float s0 = a0.x + a0.y, s1 = a1.x + a1.y;
                #pragma unroll
                for (int o = 16; o > 0; o >>= 1) {
                    s0 += __shfl_xor_sync(0xffffffffu, s0, o);
                    s1 += __shfl_xor_sync(0xffffffffu, s1, o);
                }
                if (lane == 0) {
                    g_sc[d0] = s0;
                    if (v1) g_sc[d1] = s1;
                }
            }
        }
        gbar(ep);
        // ======== Phase B: softmax (redundant per warp) + context, 3-way n-split
        {
            float csum = 0.f;
            int b = 0, ec = 0;
            if (uvalid) {
                b = q >> 4; ec = q & 15;
                float ev[7];
                float mx = -3.4e38f;
                #pragma unroll
                for (int j = 0; j < 7; j++) {
                    int n = lane + j * 32;
                    float s = (n < NREG) ? __ldcg(&g_sc[b * NREG + n]) : -3.4e38f;
                    ev[j] = s;
                    mx = fmaxf(mx, s);
                }
                mx = allmax(mx);
                float sum = 0.f;
                #pragma unroll
                for (int j = 0; j < 7; j++) {
                    int n = lane + j * 32;
                    float e = (n < NREG) ? expf(ev[j] - mx) : 0.f;
                    ev[j] = e;
                    sum += e;
                }
                sum = allsum(sum);
                float inv = 1.f / sum;
                float* ab = abuf + w * 224;
                #pragma unroll
                for (int j = 0; j < 7; j++) {
                    int n = lane + j * 32;
                    if (n < NREG) ab[n] = ev[j] * inv;
                }
                __syncwarp();
                const float* fp = F + (size_t)b * NREG * EMB + ec * 32 + lane;
                int n0 = nt3 * 65;
                int n1 = (nt3 == 2) ? 196 : (n0 + 65);
                float a8[8];
                #pragma unroll
                for (int j = 0; j < 8; j++) a8[j] = 0.f;
                int n = n0;
                for (; n + 8 <= n1; n += 8) {
                    #pragma unroll
                    for (int j = 0; j < 8; j++)
                        a8[j] = fmaf(ab[n + j], fp[(size_t)(n + j) * 512], a8[j]);
                }
                for (; n < n1; n++) a8[0] = fmaf(ab[n], fp[(size_t)n * 512], a8[0]);
                csum = ((a8[0] + a8[1]) + (a8[2] + a8[3]))
                     + ((a8[4] + a8[5]) + (a8[6] + a8[7]));
                if (nt3) redB[u * 64 + (nt3 - 1) * 32 + lane] = csum;
            }
            __syncthreads();
            if (uvalid && nt3 == 0)
                g_ctx[b * 512 + ec * 32 + lane] =
                    csum + redB[u * 64 + lane] + redB[u * 64 + 32 + lane];
        }
        gbar(ep);
        // ======== Phase C: stage ctxT; 8-way k partials (warps 0-7); reduce;
        //          fused LSTM update ========
        {
            const float4* cg = (const float4*)g_ctx;
            for (int i = tid; i < 4096; i += RTHREADS) {
                float4 v = __ldcg(cg + i);
                act4[(128 + (i & 127)) * 33 + (i >> 7)] = v;
            }
            __syncthreads();
            if (w < 8) {
                const int side = w >> 2;              // 0:h rows  1:ctx rows
                const int qt = w & 3;
                const int baseRow = side * 128 + qt * 32;
                const int srcOff = side ? 0 : 2048;   // ctx->M(src0), h->Whh(src1)
                float2 pacc[4][4];
                #pragma unroll
                for (int uu = 0; uu < 4; uu++)
                    #pragma unroll
                    for (int g = 0; g < 4; g++) pacc[uu][g] = make_float2(0.f, 0.f);
                const float4* actp = act4 + (size_t)baseRow * 33 + lane;
                #pragma unroll 2
                for (int k4l = 0; k4l < 32; k4l++) {
                    float4 x = actp[k4l * 33];
                    #pragma unroll
                    for (int uu = 0; uu < 4; uu++) {
                        const float4* wp = (const float4*)(ws + uu * 4096 + srcOff)
                                         + qt * 32 + k4l;
                        #pragma unroll
                        for (int g = 0; g < 4; g++) {
                            float4 wg = wp[g * 128];
                            ffma2(pacc[uu][g], make_float2(wg.x, wg.y),
                                               make_float2(x.x, x.y));
                            ffma2(pacc[uu][g], make_float2(wg.z, wg.w),
                                               make_float2(x.z, x.w));
                        }
                    }
                }
                float* rC = redC2 + w * 512;
                #pragma unroll
                for (int uu = 0; uu < 4; uu++)
                    #pragma unroll
                    for (int g = 0; g < 4; g++)
                        rC[(uu * 4 + g) * 32 + lane] = pacc[uu][g].x + pacc[uu][g].y;
            }
            __syncthreads();
            if (w < 4 && uvalid) {                    // u == w here
                float gate[4];
                #pragma unroll
                for (int g = 0; g < 4; g++) {
                    float s = 0.f;
                    #pragma unroll
                    for (int j = 0; j < 8; j++)
                        s += redC2[j * 512 + (w * 4 + g) * 32 + lane];
                    gate[g] = s + pre[g] + biasq[g];
                }
                float si = 1.f / (1.f + expf(-gate[0]));
                float sf = 1.f / (1.f + expf(-gate[1]));
                float so = 1.f / (1.f + expf(-gate[3]));
                c_l = sf * c_l + si * tanhf(gate[2]);
                float h2v = so * tanhf(c_l);
                g_h[lane * 512 + q] = h2v;
                g_Ht[(size_t)((lane << 6) + t) * 512 + q] = f2tf32(h2v);
            }
        }
        gbar(ep);
    }
}

// ---------------- launch ----------------
extern "C" void kernel_launch(void* const* d_in, const int* in_sizes, int n_in,
                              void* d_out, int out_size) {
    const float* features = (const float*)d_in[0];
    const int*   captions = (const int*)  d_in[1];
    const float* embW     = (const float*)d_in[2];
    const float* ihW      = (const float*)d_in[3];
    const float* ihb      = (const float*)d_in[4];
    const float* icW      = (const float*)d_in[5];
    const float* icb      = (const float*)d_in[6];
    const float* rW       = (const float*)d_in[7];
    const float* rb       = (const float*)d_in[8];
    const float* Wih      = (const float*)d_in[9];
    const float* Whh      = (const float*)d_in[10];
    const float* bih      = (const float*)d_in[11];
    const float* bhh      = (const float*)d_in[12];
    const float* oW       = (const float*)d_in[13];
    const float* ob       = (const float*)d_in[14];
    float* out = (float*)d_out;

    static int inited = 0;
    static float *pXe, *pPre;
    if (!inited) {
        cudaFuncSetAttribute(k_rec, cudaFuncAttributeMaxDynamicSharedMemorySize, 228864);
        cudaFuncSetAttribute(k_out_tc, cudaFuncAttributeMaxDynamicSharedMemorySize, 110592);
        cudaGetSymbolAddress((void**)&pXe,  g_xe);
        cudaGetSymbolAddress((void**)&pPre, g_pre2T);
        inited = 1;
    }

    // launch 0: fused prep (embed + rW1 transpose + init(own fmean) + cvtW)
    k_prep<<<20416, 256>>>(captions, embW, rW, features, ihW, ihb, icW, icb, oW);
    // launch 1: fused xe + M hoists
    k_gemmXM<<<dim3(8, 16, 2), 256>>>(rW, rb, Wih);
    // launch 2: pre2T = xe @ Wih^T (transposed output layout)
    k_gemm64<<<dim3(32, 16), 256>>>(pXe, 512, Wih, 512, nullptr, pPre, 0, 1);
    // launch 3: recurrence (384 threads)  <-- ncu profiles this slot
    k_rec<<<NCTA, RTHREADS, 228864>>>(features, Whh, bih, bhh);
    // launch 4: batched output projection (tf32 MMA, 256x128 tiles, streaming stores)
    k_out_tc<<<dim3(8, 250), 256, 110592>>>(ob, out);
}